// round 7
// baseline (speedup 1.0000x reference)
#include <cuda_runtime.h>
#include <cuda_bf16.h>
#include <math.h>
#include <stdint.h>

// Problem dims (fixed)
#define TT 512
#define BB 512
#define DD 512
#define HH 512
#define BH (BB * HH)  // 262144

// -------------------- device scratch (no allocations allowed) --------------
__device__ float          g_xp[(size_t)TT * BH];            // 512 MB
__device__ __nv_bfloat16  g_wih_h[HH * DD], g_wih_l[HH * DD];
__device__ __nv_bfloat16  g_whh_h[HH * HH], g_whh_l[HH * HH];
__device__ __nv_bfloat16  g_hhi[2][BH], g_hlo[2][BH];

// producer flags: flag[m][n*32] = monotonic count of h productions by CTA (m,n).
__device__ unsigned g_flag[16][8 * 32];

// -------------------- PTX helpers (sm_80-level only; no 'a' features) ------
__device__ __forceinline__ uint32_t smem_u32(const void* p) {
    uint32_t a;
    asm("{ .reg .u64 t; cvta.to.shared.u64 t, %1; cvt.u32.u64 %0, t; }" : "=r"(a) : "l"(p));
    return a;
}
__device__ __forceinline__ void cp16(uint32_t s, const void* g) {
    asm volatile("cp.async.cg.shared.global [%0], [%1], 16;" :: "r"(s), "l"(g));
}
#define CP_COMMIT() asm volatile("cp.async.commit_group;" ::: "memory")
#define CP_WAIT(n)  asm volatile("cp.async.wait_group %0;" :: "n"(n) : "memory")

__device__ __forceinline__ void ldsm4(uint32_t* r, uint32_t addr) {
    asm volatile("ldmatrix.sync.aligned.m8n8.x4.shared.b16 {%0,%1,%2,%3}, [%4];"
                 : "=r"(r[0]), "=r"(r[1]), "=r"(r[2]), "=r"(r[3]) : "r"(addr));
}
__device__ __forceinline__ void mma16816(float* d, const uint32_t* a, uint32_t b0, uint32_t b1) {
    asm volatile("mma.sync.aligned.m16n8k16.row.col.f32.bf16.bf16.f32 "
                 "{%0,%1,%2,%3}, {%4,%5,%6,%7}, {%8,%9}, {%0,%1,%2,%3};"
                 : "+f"(d[0]), "+f"(d[1]), "+f"(d[2]), "+f"(d[3])
                 : "r"(a[0]), "r"(a[1]), "r"(a[2]), "r"(a[3]), "r"(b0), "r"(b1));
}

// fast tanh: 1 - 2/(e^{2x}+1) via MUFU (abs err ~1e-6; saturates correctly)
__device__ __forceinline__ float fast_tanh(float x) {
    float e = __expf(2.0f * x);
    return 1.0f - __fdividef(2.0f, e + 1.0f);
}

// -------------------- split helpers ----------------------------------------
__device__ __forceinline__ void split1(float x, __nv_bfloat16& h, __nv_bfloat16& l) {
    h = __float2bfloat16_rn(x);
    l = __float2bfloat16_rn(x - __bfloat162float(h));
}

__global__ __launch_bounds__(256) void split_kernel(const float* __restrict__ src,
                                                    __nv_bfloat16* __restrict__ hi,
                                                    __nv_bfloat16* __restrict__ lo, int n4) {
    for (int i = blockIdx.x * blockDim.x + threadIdx.x; i < n4; i += gridDim.x * blockDim.x) {
        float4 v = ((const float4*)src)[i];
        __nv_bfloat16 h0, h1, h2, h3, l0, l1, l2, l3;
        split1(v.x, h0, l0); split1(v.y, h1, l1);
        split1(v.z, h2, l2); split1(v.w, h3, l3);
        __nv_bfloat162* ph = (__nv_bfloat162*)hi;
        __nv_bfloat162* pl = (__nv_bfloat162*)lo;
        ph[i * 2] = __nv_bfloat162(h0, h1); ph[i * 2 + 1] = __nv_bfloat162(h2, h3);
        pl[i * 2] = __nv_bfloat162(l0, l1); pl[i * 2 + 1] = __nv_bfloat162(l2, l3);
    }
}

// -------------------- async tile loader (64-col bf16 tiles) ----------------
template <int ROWS, int THREADS>
__device__ __forceinline__ void load_tile_async(const __nv_bfloat16* __restrict__ g,
                                                size_t row0, int kbase,
                                                uint32_t sdst, int tid) {
    constexpr int TOT = ROWS * 8;  // 16B granules
#pragma unroll
    for (int i = 0; i < TOT / THREADS; ++i) {
        int v = i * THREADS + tid;
        int row = v >> 3, g16 = v & 7;
        uint32_t off = (uint32_t)(row * 128 + ((g16 * 16) ^ ((row & 7) * 16)));
        cp16(sdst + off, g + (row0 + (size_t)row) * HH + kbase + g16 * 8);
    }
}

// -------------------- xp GEMM with fused X split ---------------------------
// xp[M=T*B, N=H] = X[M,D](fp32) @ (Wih hi/lo)[N,D]^T + (bih + bhh)
// BM=128, BN=128, BK=64, 256 threads. X loaded fp32 to padded staging,
// converted in-kernel to swizzled bf16 hi/lo (bit-identical to split_kernel).
#define XA_H(s) ((uint32_t)((s) * 32768))
#define XA_L(s) (XA_H(s) + 16384u)
#define XB_H(s) ((uint32_t)(65536 + (s) * 32768))
#define XB_L(s) (XB_H(s) + 16384u)
#define XSTG(s) ((uint32_t)(131072 + (s) * 34816))   // 128 rows x 272B
#define XP_SMEM 200704

__global__ void __launch_bounds__(256, 1)
xp_gemm_fused(const float* __restrict__ X,
              const __nv_bfloat16* __restrict__ Bhi, const __nv_bfloat16* __restrict__ Blo,
              const float* __restrict__ bih, const float* __restrict__ bhh,
              float* __restrict__ out_f)
{
    extern __shared__ char smem[];
    const uint32_t sbase = smem_u32(smem);
    const int tid = threadIdx.x;
    const int wid = tid >> 5, lane = tid & 31;
    const size_t bm = (size_t)blockIdx.y * 128;
    const int bn = blockIdx.x * 128;
    const int wm = (wid & 1) * 64;          // WM=64 (BM/WM=2), WN=32 (BN/WN=4)
    const int wn = (wid >> 1) * 32;

    float acc[4][4][4];
#pragma unroll
    for (int mi = 0; mi < 4; ++mi)
#pragma unroll
        for (int ni = 0; ni < 4; ++ni)
#pragma unroll
            for (int q = 0; q < 4; ++q) acc[mi][ni][q] = 0.0f;

    const int sub = lane >> 3, li = lane & 7;
    const int arow = (sub & 1) * 8 + li;
    const int akb  = (sub >> 1) * 16;
    const int brow = (sub >> 1) * 8 + li;
    const int bkb  = (sub & 1) * 16;
    const uint32_t swx = (uint32_t)(li * 16);

    // per-chunk issue: X fp32 (8 granules/thr) + Bh + Bl (4+4 granules/thr)
    auto issue_loads = [&](int c, int s) {
        const int kb = c * 64;
#pragma unroll
        for (int i = 0; i < 8; ++i) {
            int v = i * 256 + tid;             // 2048 granules
            int row = v >> 4, g16 = v & 15;
            cp16(sbase + XSTG(s) + (uint32_t)(row * 272 + g16 * 16),
                 X + (bm + (size_t)row) * DD + kb + g16 * 4);
        }
        load_tile_async<128, 256>(Bhi, (size_t)bn, kb, sbase + XB_H(s), tid);
        load_tile_async<128, 256>(Blo, (size_t)bn, kb, sbase + XB_L(s), tid);
        CP_COMMIT();
    };

    issue_loads(0, 0);

    const int crow = tid >> 1;          // convert: thread row
    const int chalf = tid & 1;          // cols [0,32) or [32,64)

    for (int c = 0; c < 8; ++c) {
        const int s = c & 1;
        if (c + 1 < 8) {
            issue_loads(c + 1, s ^ 1);
            CP_WAIT(1);
        } else {
            CP_WAIT(0);
        }
        __syncthreads();

        // convert X chunk: fp32 staging -> swizzled bf16 hi/lo
        {
            const char* stg = smem + XSTG(s) + crow * 272 + chalf * 128;
#pragma unroll
            for (int q2 = 0; q2 < 4; ++q2) {
                float4 u = *(const float4*)(stg + q2 * 32);
                float4 v = *(const float4*)(stg + q2 * 32 + 16);
                __nv_bfloat16 h[8], l[8];
                split1(u.x, h[0], l[0]); split1(u.y, h[1], l[1]);
                split1(u.z, h[2], l[2]); split1(u.w, h[3], l[3]);
                split1(v.x, h[4], l[4]); split1(v.y, h[5], l[5]);
                split1(v.z, h[6], l[6]); split1(v.w, h[7], l[7]);
                uint4 hv, lv;
                {
                    __nv_bfloat162 p0(h[0], h[1]), p1(h[2], h[3]), p2(h[4], h[5]), p3(h[6], h[7]);
                    hv = make_uint4(*(uint32_t*)&p0, *(uint32_t*)&p1,
                                    *(uint32_t*)&p2, *(uint32_t*)&p3);
                    __nv_bfloat162 q0(l[0], l[1]), q1(l[2], l[3]), q2p(l[4], l[5]), q3(l[6], l[7]);
                    lv = make_uint4(*(uint32_t*)&q0, *(uint32_t*)&q1,
                                    *(uint32_t*)&q2p, *(uint32_t*)&q3);
                }
                uint32_t bytecol = (uint32_t)((chalf * 4 + q2) * 16);
                uint32_t off = (uint32_t)(crow * 128) + (bytecol ^ (((uint32_t)(crow & 7)) << 4));
                *(uint4*)(smem + XA_H(s) + off) = hv;
                *(uint4*)(smem + XA_L(s) + off) = lv;
            }
        }
        __syncthreads();

        const uint32_t aHi = sbase + XA_H(s) + (uint32_t)((wm + arow) * 128);
        const uint32_t aLo = aHi + 16384;
        const uint32_t bHi = sbase + XB_H(s) + (uint32_t)((wn + brow) * 128);
        const uint32_t bLo = bHi + 16384;

#pragma unroll
        for (int kk = 0; kk < 4; ++kk) {
            const uint32_t ka = (uint32_t)(kk * 32 + akb) ^ swx;
            const uint32_t kb2 = (uint32_t)(kk * 32 + bkb) ^ swx;
            uint32_t ah[4][4], al[4][4], bh[2][4], bl[2][4];
#pragma unroll
            for (int mi = 0; mi < 4; ++mi) {
                ldsm4(ah[mi], aHi + mi * 2048 + ka);
                ldsm4(al[mi], aLo + mi * 2048 + ka);
            }
#pragma unroll
            for (int nj = 0; nj < 2; ++nj) {
                ldsm4(bh[nj], bHi + nj * 2048 + kb2);
                ldsm4(bl[nj], bLo + nj * 2048 + kb2);
            }
#pragma unroll
            for (int mi = 0; mi < 4; ++mi)
#pragma unroll
                for (int ni = 0; ni < 4; ++ni)
                    mma16816(acc[mi][ni], ah[mi],
                             bh[ni >> 1][2 * (ni & 1)], bh[ni >> 1][2 * (ni & 1) + 1]);
#pragma unroll
            for (int mi = 0; mi < 4; ++mi)
#pragma unroll
                for (int ni = 0; ni < 4; ++ni)
                    mma16816(acc[mi][ni], ah[mi],
                             bl[ni >> 1][2 * (ni & 1)], bl[ni >> 1][2 * (ni & 1) + 1]);
#pragma unroll
            for (int mi = 0; mi < 4; ++mi)
#pragma unroll
                for (int ni = 0; ni < 4; ++ni)
                    mma16816(acc[mi][ni], al[mi],
                             bh[ni >> 1][2 * (ni & 1)], bh[ni >> 1][2 * (ni & 1) + 1]);
        }
        __syncthreads();
    }

    const int g = lane >> 2, tg = lane & 3;
#pragma unroll
    for (int mi = 0; mi < 4; ++mi) {
#pragma unroll
        for (int ni = 0; ni < 4; ++ni) {
            const size_t r0 = bm + (size_t)(wm + mi * 16 + g);
            const size_t r1 = r0 + 8;
            const int c0 = bn + wn + ni * 8 + 2 * tg;
            float b0 = bih[c0] + bhh[c0];
            float b1 = bih[c0 + 1] + bhh[c0 + 1];
            *(float2*)(out_f + r0 * HH + c0) =
                make_float2(acc[mi][ni][0] + b0, acc[mi][ni][1] + b1);
            *(float2*)(out_f + r1 * HH + c0) =
                make_float2(acc[mi][ni][2] + b0, acc[mi][ni][3] + b1);
        }
    }
}

// -------------------- persistent recurrence kernel -------------------------
// 128 CTAs (one/SM), 256 threads. CTA tile 32(M)x64(N). W_hh resident in smem.
// Step order: poll -> issue loads -> self-chunk compute (covers latency) ->
// staged peer computes -> epilogue -> release flag.
#define NCTA 128
#define PBM 32
#define PBN 64
#define SMB 0
#define SMB_SPLIT 65536
#define SMB_CHUNK 8192
#define SMA 131072
#define SMA_CHUNK 8192
#define SMXP 196608
#define SMMISC 204800
#define PSMEM 204928

__global__ void __launch_bounds__(256, 1)
rnn_persistent_kernel(const float* __restrict__ xp,
                      const __nv_bfloat16* __restrict__ whh_h,
                      const __nv_bfloat16* __restrict__ whh_l,
                      __nv_bfloat16* __restrict__ hhi, __nv_bfloat16* __restrict__ hlo,
                      float* __restrict__ out)
{
    extern __shared__ char smem[];
    const uint32_t sb = smem_u32(smem);
    const int tid = threadIdx.x;
    const int wid = tid >> 5, lane = tid & 31;
    const int mtile = blockIdx.x >> 3;      // 0..15
    const int ntile = blockIdx.x & 7;       // 0..7
    const size_t bm = (size_t)mtile * PBM;
    const int bn = ntile * PBN;
    const int wm = (wid & 1) * 16;
    const int wn = (wid >> 1) * 16;

    if (tid == 0) {
        unsigned fb0;
        asm volatile("ld.volatile.global.u32 %0, [%1];"
                     : "=r"(fb0) : "l"(&g_flag[mtile][ntile * 32]));
        *(unsigned*)(smem + SMMISC) = fb0;
    }

    // resident W_hh tiles
#pragma unroll
    for (int i = 0; i < 32; ++i) {
        int v = i * 256 + tid;
        int split = v >> 12;
        int rem = v & 4095;
        int chunk = rem >> 9;
        int rr = rem & 511;
        int row = rr >> 3, g16 = rr & 7;
        const __nv_bfloat16* src = (split ? whh_l : whh_h);
        uint32_t dst = sb + SMB + split * SMB_SPLIT + chunk * SMB_CHUNK
                     + row * 128 + (uint32_t)((g16 * 16) ^ ((row & 7) * 16));
        cp16(dst, src + (size_t)(bn + row) * HH + chunk * 64 + g16 * 8);
    }
    CP_COMMIT();

    auto sts4 = [&](uint32_t base, int row, int lc, uint32_t val) {
        uint32_t bc = (uint32_t)(lc * 2);
        uint32_t off = (uint32_t)(row * 128)
                     + ((bc & ~15u) ^ (((uint32_t)(row & 7)) << 4)) + (bc & 15u);
        *(uint32_t*)(smem + base + off) = val;
    };
    const uint32_t selfA = (uint32_t)(SMA + ntile * SMA_CHUNK);

    // step 0: h1 = tanh(xp_0)
#pragma unroll
    for (int i = 0; i < 2; ++i) {
        int v = i * 256 + tid;
        int row = v >> 4, c4 = v & 15;
        const float4 x = *(const float4*)(xp + (bm + row) * HH + bn + c4 * 4);
        float v0 = fast_tanh(x.x), v1 = fast_tanh(x.y);
        float v2 = fast_tanh(x.z), v3 = fast_tanh(x.w);
        __nv_bfloat16 h0, l0, h1, l1, h2, l2, h3, l3;
        split1(v0, h0, l0); split1(v1, h1, l1);
        split1(v2, h2, l2); split1(v3, h3, l3);
        __nv_bfloat162 hp0(h0, h1), hp1(h2, h3), lp0(l0, l1), lp1(l2, l3);
        size_t off = (bm + row) * HH + bn + c4 * 4;
        *(uint2*)(hhi + off) = make_uint2(*(uint32_t*)&hp0, *(uint32_t*)&hp1);
        *(uint2*)(hlo + off) = make_uint2(*(uint32_t*)&lp0, *(uint32_t*)&lp1);
        sts4(selfA, row, c4 * 4, *(uint32_t*)&hp0);
        sts4(selfA, row, c4 * 4 + 2, *(uint32_t*)&hp1);
        sts4(selfA + 4096, row, c4 * 4, *(uint32_t*)&lp0);
        sts4(selfA + 4096, row, c4 * 4 + 2, *(uint32_t*)&lp1);
    }
    CP_WAIT(0);
    __syncthreads();
    const unsigned fb = *(const unsigned*)(smem + SMMISC);
    if (tid == 0)
        asm volatile("red.release.gpu.global.add.u32 [%0], %1;"
                     :: "l"(&g_flag[mtile][ntile * 32]), "r"(1u) : "memory");

    const int sub = lane >> 3, li = lane & 7;
    const int arow = (sub & 1) * 8 + li;
    const int akb  = (sub >> 1) * 16;
    const int brow = (sub >> 1) * 8 + li;
    const int bkb  = (sub & 1) * 16;
    const uint32_t swx = (uint32_t)(li * 16);
    const int g = lane >> 2, tg = lane & 3;

    for (int t = 1; t < TT; ++t) {
        const __nv_bfloat16* Ah = hhi;
        const __nv_bfloat16* Al = hlo;
        const float* xpt = xp + (size_t)t * BH;

        float acc[2][4];
#pragma unroll
        for (int ni = 0; ni < 2; ++ni)
#pragma unroll
            for (int q = 0; q < 4; ++q) acc[ni][q] = 0.0f;

        auto compute_chunk = [&](int c) {
            const uint32_t aHi = sb + SMA + c * SMA_CHUNK + (uint32_t)((wm + arow) * 128);
            const uint32_t aLo = aHi + 4096;
            const uint32_t bHi = sb + SMB + c * SMB_CHUNK + (uint32_t)((wn + brow) * 128);
            const uint32_t bLo = bHi + SMB_SPLIT;
#pragma unroll
            for (int kk = 0; kk < 4; ++kk) {
                const uint32_t ka  = (uint32_t)(kk * 32 + akb) ^ swx;
                const uint32_t kb2 = (uint32_t)(kk * 32 + bkb) ^ swx;
                uint32_t ah[4], al4[4], bh[4], bl[4];
                ldsm4(ah, aHi + ka);
                ldsm4(al4, aLo + ka);
                ldsm4(bh, bHi + kb2);
                ldsm4(bl, bLo + kb2);
#pragma unroll
                for (int ni = 0; ni < 2; ++ni)
                    mma16816(acc[ni], ah, bh[2 * ni], bh[2 * ni + 1]);
#pragma unroll
                for (int ni = 0; ni < 2; ++ni)
                    mma16816(acc[ni], ah, bl[2 * ni], bl[2 * ni + 1]);
#pragma unroll
                for (int ni = 0; ni < 2; ++ni)
                    mma16816(acc[ni], al4, bh[2 * ni], bh[2 * ni + 1]);
            }
        };

        // phase A: poll the 7 peer producers of h_t
        if (tid < 7) {
            const int c = (ntile + 1 + tid) & 7;
            const unsigned* fl = &g_flag[mtile][c * 32];
            const unsigned target = fb + (unsigned)t;
            unsigned v;
            do {
                asm volatile("ld.acquire.gpu.global.u32 %0, [%1];" : "=r"(v) : "l"(fl));
            } while ((int)(v - target) < 0);
        }
        __syncthreads();

        // phase B: issue loads — xp first, then 7 peer chunks (8 groups)
        {
#pragma unroll
            for (int i = 0; i < 2; ++i) {
                int v = i * 256 + tid;
                int row = v >> 4, g16 = v & 15;
                cp16(sb + SMXP + row * 256 + g16 * 16,
                     xpt + (bm + row) * HH + bn + g16 * 4);
            }
            CP_COMMIT();
        }
#pragma unroll
        for (int j = 1; j < 8; ++j) {
            const int c = (ntile + j) & 7;
            const uint32_t base = sb + SMA + c * SMA_CHUNK;
#pragma unroll
            for (int i = 0; i < 2; ++i) {
                int v = i * 256 + tid;
                int split = v >> 8;
                int rr = v & 255;
                int row = rr >> 3, g16 = rr & 7;
                const __nv_bfloat16* src = (split ? Al : Ah);
                uint32_t dst = base + split * 4096 + row * 128
                             + (uint32_t)((g16 * 16) ^ ((row & 7) * 16));
                cp16(dst, src + (bm + (size_t)row) * HH + c * 64 + g16 * 8);
            }
            CP_COMMIT();
        }

        // phase C: self chunk compute while loads are in flight
        compute_chunk(ntile);

        // phase D: staged waits + peer chunk computes
#pragma unroll
        for (int j = 1; j < 8; j += 2) {
            if (j == 1)      { CP_WAIT(5); }
            else if (j == 3) { CP_WAIT(3); }
            else if (j == 5) { CP_WAIT(1); }
            else             { CP_WAIT(0); }
            __syncthreads();
            compute_chunk((ntile + j) & 7);
            if (j + 1 < 8) compute_chunk((ntile + j + 1) & 7);
        }

        // phase E: epilogue
        const float* sXP = (const float*)(smem + SMXP);
#pragma unroll
        for (int ni = 0; ni < 2; ++ni) {
            const int lr0 = wm + g;
            const int lc  = wn + ni * 8 + 2 * tg;
            const size_t r0 = bm + (size_t)lr0;
            const size_t r1 = r0 + 8;
            const int c0 = bn + lc;
            float2 x0 = *(const float2*)(sXP + lr0 * PBN + lc);
            float2 x1 = *(const float2*)(sXP + (lr0 + 8) * PBN + lc);
            float v0 = fast_tanh(acc[ni][0] + x0.x);
            float v1 = fast_tanh(acc[ni][1] + x0.y);
            float v2 = fast_tanh(acc[ni][2] + x1.x);
            float v3 = fast_tanh(acc[ni][3] + x1.y);
            if (t == TT - 1) {
                *(float2*)(out + r0 * HH + c0) = make_float2(v0, v1);
                *(float2*)(out + r1 * HH + c0) = make_float2(v2, v3);
            } else {
                __nv_bfloat16 h0, l0, h1, l1, h2, l2, h3, l3;
                split1(v0, h0, l0); split1(v1, h1, l1);
                split1(v2, h2, l2); split1(v3, h3, l3);
                __nv_bfloat162 hp0(h0, h1), hp1(h2, h3), lp0(l0, l1), lp1(l2, l3);
                *(uint32_t*)(hhi + r0 * HH + c0) = *(uint32_t*)&hp0;
                *(uint32_t*)(hlo + r0 * HH + c0) = *(uint32_t*)&lp0;
                *(uint32_t*)(hhi + r1 * HH + c0) = *(uint32_t*)&hp1;
                *(uint32_t*)(hlo + r1 * HH + c0) = *(uint32_t*)&lp1;
                sts4(selfA, lr0, lc, *(uint32_t*)&hp0);
                sts4(selfA + 4096, lr0, lc, *(uint32_t*)&lp0);
                sts4(selfA, lr0 + 8, lc, *(uint32_t*)&hp1);
                sts4(selfA + 4096, lr0 + 8, lc, *(uint32_t*)&lp1);
            }
        }

        __syncthreads();
        if (tid == 0 && t < TT - 1)
            asm volatile("red.release.gpu.global.add.u32 [%0], %1;"
                         :: "l"(&g_flag[mtile][ntile * 32]), "r"(1u) : "memory");
    }
}

// -------------------- launcher ---------------------------------------------
extern "C" void kernel_launch(void* const* d_in, const int* in_sizes, int n_in,
                              void* d_out, int out_size)
{
    const float* X   = (const float*)d_in[0];
    const float* Wih = (const float*)d_in[1];
    const float* Whh = (const float*)d_in[2];
    const float* bih = (const float*)d_in[3];
    const float* bhh = (const float*)d_in[4];
    float* out = (float*)d_out;

    float* xp;
    __nv_bfloat16 *wih_h, *wih_l, *whh_h, *whh_l, *hhi, *hlo;
    cudaGetSymbolAddress((void**)&xp, g_xp);
    cudaGetSymbolAddress((void**)&wih_h, g_wih_h);
    cudaGetSymbolAddress((void**)&wih_l, g_wih_l);
    cudaGetSymbolAddress((void**)&whh_h, g_whh_h);
    cudaGetSymbolAddress((void**)&whh_l, g_whh_l);
    cudaGetSymbolAddress((void**)&hhi, g_hhi);
    cudaGetSymbolAddress((void**)&hlo, g_hlo);

    cudaFuncSetAttribute(xp_gemm_fused,
                         cudaFuncAttributeMaxDynamicSharedMemorySize, XP_SMEM);
    cudaFuncSetAttribute(rnn_persistent_kernel,
                         cudaFuncAttributeMaxDynamicSharedMemorySize, PSMEM);

    // 1) hi/lo splits of the two weight matrices (X split is fused in-GEMM)
    split_kernel<<<128, 256>>>(Wih, wih_h, wih_l, HH * DD / 4);
    split_kernel<<<128, 256>>>(Whh, whh_h, whh_l, HH * HH / 4);

    // 2) xp = X @ Wih^T + (b_ih + b_hh), fused X split
    {
        dim3 g(HH / 128, (TT * BB) / 128);  // (4, 2048)
        xp_gemm_fused<<<g, 256, XP_SMEM>>>(X, wih_h, wih_l, bih, bhh, xp);
    }

    // 3) entire recurrence in one persistent kernel
    rnn_persistent_kernel<<<NCTA, 256, PSMEM>>>(xp, whh_h, whh_l, hhi, hlo, out);
}

// round 8
// speedup vs baseline: 1.6222x; 1.6222x over previous
#include <cuda_runtime.h>
#include <cuda_bf16.h>
#include <math.h>
#include <stdint.h>

// Problem dims (fixed)
#define TT 512
#define BB 512
#define DD 512
#define HH 512
#define BH (BB * HH)  // 262144

// -------------------- device scratch (no allocations allowed) --------------
__device__ float          g_xp[(size_t)TT * BH];            // 512 MB
__device__ __nv_bfloat16  g_xhi[(size_t)TT * BB * DD];      // 256 MB
__device__ __nv_bfloat16  g_xlo[(size_t)TT * BB * DD];      // 256 MB
__device__ __nv_bfloat16  g_wih_h[HH * DD], g_wih_l[HH * DD];
__device__ __nv_bfloat16  g_whh_h[HH * HH], g_whh_l[HH * HH];
__device__ __nv_bfloat16  g_hhi[2][BH], g_hlo[2][BH];

// producer flags: flag[m][n*32] = monotonic count of h productions by CTA (m,n).
__device__ unsigned g_flag[16][8 * 32];

// -------------------- PTX helpers (sm_80-level only; no 'a' features) ------
__device__ __forceinline__ uint32_t smem_u32(const void* p) {
    uint32_t a;
    asm("{ .reg .u64 t; cvta.to.shared.u64 t, %1; cvt.u32.u64 %0, t; }" : "=r"(a) : "l"(p));
    return a;
}
__device__ __forceinline__ void cp16(uint32_t s, const void* g) {
    asm volatile("cp.async.cg.shared.global [%0], [%1], 16;" :: "r"(s), "l"(g));
}
#define CP_COMMIT() asm volatile("cp.async.commit_group;" ::: "memory")
#define CP_WAIT(n)  asm volatile("cp.async.wait_group %0;" :: "n"(n) : "memory")

__device__ __forceinline__ void ldsm4(uint32_t* r, uint32_t addr) {
    asm volatile("ldmatrix.sync.aligned.m8n8.x4.shared.b16 {%0,%1,%2,%3}, [%4];"
                 : "=r"(r[0]), "=r"(r[1]), "=r"(r[2]), "=r"(r[3]) : "r"(addr));
}
__device__ __forceinline__ void mma16816(float* d, const uint32_t* a, uint32_t b0, uint32_t b1) {
    asm volatile("mma.sync.aligned.m16n8k16.row.col.f32.bf16.bf16.f32 "
                 "{%0,%1,%2,%3}, {%4,%5,%6,%7}, {%8,%9}, {%0,%1,%2,%3};"
                 : "+f"(d[0]), "+f"(d[1]), "+f"(d[2]), "+f"(d[3])
                 : "r"(a[0]), "r"(a[1]), "r"(a[2]), "r"(a[3]), "r"(b0), "r"(b1));
}

// fast tanh: 1 - 2/(e^{2x}+1) via MUFU (abs err ~1e-6; saturates correctly)
__device__ __forceinline__ float fast_tanh(float x) {
    float e = __expf(2.0f * x);
    return 1.0f - __fdividef(2.0f, e + 1.0f);
}

// -------------------- split helpers ----------------------------------------
__device__ __forceinline__ void split1(float x, __nv_bfloat16& h, __nv_bfloat16& l) {
    h = __float2bfloat16_rn(x);
    l = __float2bfloat16_rn(x - __bfloat162float(h));
}

__global__ __launch_bounds__(256) void split_kernel(const float* __restrict__ src,
                                                    __nv_bfloat16* __restrict__ hi,
                                                    __nv_bfloat16* __restrict__ lo, int n4) {
    for (int i = blockIdx.x * blockDim.x + threadIdx.x; i < n4; i += gridDim.x * blockDim.x) {
        float4 v = ((const float4*)src)[i];
        __nv_bfloat16 h0, h1, h2, h3, l0, l1, l2, l3;
        split1(v.x, h0, l0); split1(v.y, h1, l1);
        split1(v.z, h2, l2); split1(v.w, h3, l3);
        __nv_bfloat162* ph = (__nv_bfloat162*)hi;
        __nv_bfloat162* pl = (__nv_bfloat162*)lo;
        ph[i * 2] = __nv_bfloat162(h0, h1); ph[i * 2 + 1] = __nv_bfloat162(h2, h3);
        pl[i * 2] = __nv_bfloat162(l0, l1); pl[i * 2 + 1] = __nv_bfloat162(l2, l3);
    }
}

// -------------------- async tile loader (64-col bf16 tiles) ----------------
template <int ROWS, int THREADS>
__device__ __forceinline__ void load_tile_async(const __nv_bfloat16* __restrict__ g,
                                                size_t row0, int kbase,
                                                uint32_t sdst, int tid) {
    constexpr int TOT = ROWS * 8;  // 16B granules
#pragma unroll
    for (int i = 0; i < TOT / THREADS; ++i) {
        int v = i * THREADS + tid;
        int row = v >> 3, g16 = v & 7;
        uint32_t off = (uint32_t)(row * 128 + ((g16 * 16) ^ ((row & 7) * 16)));
        cp16(sdst + off, g + (row0 + (size_t)row) * HH + kbase + g16 * 8);
    }
}

// -------------------- xp GEMM (2 CTAs/SM tile) -----------------------------
// xp[M, N] = (Ahi+Alo)[M,K] @ (Bhi+Blo)[N,K]^T + bih + bhh; K=512, BK=64.
template <int BM, int BN, int WM, int WN>
__global__ void __launch_bounds__((BM / WM) * (BN / WN) * 32, 2)
gemm_split_kernel(const __nv_bfloat16* __restrict__ Ahi, const __nv_bfloat16* __restrict__ Alo,
                  const __nv_bfloat16* __restrict__ Bhi, const __nv_bfloat16* __restrict__ Blo,
                  const float* __restrict__ bih, const float* __restrict__ bhh,
                  float* __restrict__ out_f)
{
    constexpr int THREADS = (BM / WM) * (BN / WN) * 32;
    constexpr int SA = BM * 128;
    constexpr int SB = BN * 128;
    constexpr int STAGE = 2 * SA + 2 * SB;
    constexpr int NCHUNK = HH / 64;

    extern __shared__ char smem[];
    const uint32_t sbase = smem_u32(smem);
    const int tid = threadIdx.x;
    const int wid = tid >> 5, lane = tid & 31;
    const size_t bm = (size_t)blockIdx.y * BM;
    const int bn = blockIdx.x * BN;
    const int wm = (wid % (BM / WM)) * WM;
    const int wn = (wid / (BM / WM)) * WN;

    float acc[WM / 16][WN / 8][4];
#pragma unroll
    for (int mi = 0; mi < WM / 16; ++mi)
#pragma unroll
        for (int ni = 0; ni < WN / 8; ++ni)
#pragma unroll
            for (int q = 0; q < 4; ++q) acc[mi][ni][q] = 0.0f;

    const int sub = lane >> 3, li = lane & 7;
    const int arow = (sub & 1) * 8 + li;
    const int akb  = (sub >> 1) * 16;
    const int brow = (sub >> 1) * 8 + li;
    const int bkb  = (sub & 1) * 16;
    const uint32_t swx = (uint32_t)(li * 16);

    auto issue_loads = [&](int c, int s) {
        const uint32_t st = sbase + (uint32_t)(s * STAGE);
        const int kb = c * 64;
        load_tile_async<BM, THREADS>(Ahi, bm, kb, st, tid);
        load_tile_async<BM, THREADS>(Alo, bm, kb, st + SA, tid);
        load_tile_async<BN, THREADS>(Bhi, (size_t)bn, kb, st + 2 * SA, tid);
        load_tile_async<BN, THREADS>(Blo, (size_t)bn, kb, st + 2 * SA + SB, tid);
        CP_COMMIT();
    };

    issue_loads(0, 0);

    for (int c = 0; c < NCHUNK; ++c) {
        if (c + 1 < NCHUNK) {
            issue_loads(c + 1, (c + 1) & 1);
            CP_WAIT(1);
        } else {
            CP_WAIT(0);
        }
        __syncthreads();

        const uint32_t st = sbase + (uint32_t)((c & 1) * STAGE);
        const uint32_t aHi = st + (uint32_t)((wm + arow) * 128);
        const uint32_t aLo = aHi + SA;
        const uint32_t bHi = st + 2 * SA + (uint32_t)((wn + brow) * 128);
        const uint32_t bLo = bHi + SB;

#pragma unroll
        for (int kk = 0; kk < 4; ++kk) {
            const uint32_t ka = (uint32_t)(kk * 32 + akb) ^ swx;
            const uint32_t kb2 = (uint32_t)(kk * 32 + bkb) ^ swx;
            uint32_t ah[WM / 16][4], al[WM / 16][4], bh[WN / 16][4], bl[WN / 16][4];
#pragma unroll
            for (int mi = 0; mi < WM / 16; ++mi) {
                ldsm4(ah[mi], aHi + mi * 2048 + ka);
                ldsm4(al[mi], aLo + mi * 2048 + ka);
            }
#pragma unroll
            for (int nj = 0; nj < WN / 16; ++nj) {
                ldsm4(bh[nj], bHi + nj * 2048 + kb2);
                ldsm4(bl[nj], bLo + nj * 2048 + kb2);
            }
#pragma unroll
            for (int mi = 0; mi < WM / 16; ++mi)
#pragma unroll
                for (int ni = 0; ni < WN / 8; ++ni)
                    mma16816(acc[mi][ni], ah[mi],
                             bh[ni >> 1][2 * (ni & 1)], bh[ni >> 1][2 * (ni & 1) + 1]);
#pragma unroll
            for (int mi = 0; mi < WM / 16; ++mi)
#pragma unroll
                for (int ni = 0; ni < WN / 8; ++ni)
                    mma16816(acc[mi][ni], ah[mi],
                             bl[ni >> 1][2 * (ni & 1)], bl[ni >> 1][2 * (ni & 1) + 1]);
#pragma unroll
            for (int mi = 0; mi < WM / 16; ++mi)
#pragma unroll
                for (int ni = 0; ni < WN / 8; ++ni)
                    mma16816(acc[mi][ni], al[mi],
                             bh[ni >> 1][2 * (ni & 1)], bh[ni >> 1][2 * (ni & 1) + 1]);
        }
        __syncthreads();
    }

    const int g = lane >> 2, tg = lane & 3;
#pragma unroll
    for (int mi = 0; mi < WM / 16; ++mi) {
#pragma unroll
        for (int ni = 0; ni < WN / 8; ++ni) {
            const size_t r0 = bm + (size_t)(wm + mi * 16 + g);
            const size_t r1 = r0 + 8;
            const int c0 = bn + wn + ni * 8 + 2 * tg;
            float b0 = bih[c0] + bhh[c0];
            float b1 = bih[c0 + 1] + bhh[c0 + 1];
            *(float2*)(out_f + r0 * HH + c0) =
                make_float2(acc[mi][ni][0] + b0, acc[mi][ni][1] + b1);
            *(float2*)(out_f + r1 * HH + c0) =
                make_float2(acc[mi][ni][2] + b0, acc[mi][ni][3] + b1);
        }
    }
}

// -------------------- persistent recurrence kernel -------------------------
// Round-6 proven structure; only change: xp load issued at step top.
#define NCTA 128
#define PBM 32
#define PBN 64
#define SMB 0
#define SMB_SPLIT 65536
#define SMB_CHUNK 8192
#define SMA 131072
#define SMA_CHUNK 8192
#define SMXP 196608
#define SMMISC 204800
#define PSMEM 204928

__global__ void __launch_bounds__(256, 1)
rnn_persistent_kernel(const float* __restrict__ xp,
                      const __nv_bfloat16* __restrict__ whh_h,
                      const __nv_bfloat16* __restrict__ whh_l,
                      __nv_bfloat16* __restrict__ hhi, __nv_bfloat16* __restrict__ hlo,
                      float* __restrict__ out)
{
    extern __shared__ char smem[];
    const uint32_t sb = smem_u32(smem);
    const int tid = threadIdx.x;
    const int wid = tid >> 5, lane = tid & 31;
    const int mtile = blockIdx.x >> 3;      // 0..15
    const int ntile = blockIdx.x & 7;       // 0..7
    const size_t bm = (size_t)mtile * PBM;
    const int bn = ntile * PBN;
    const int wm = (wid & 1) * 16;
    const int wn = (wid >> 1) * 16;

    if (tid == 0) {
        unsigned fb0;
        asm volatile("ld.volatile.global.u32 %0, [%1];"
                     : "=r"(fb0) : "l"(&g_flag[mtile][ntile * 32]));
        *(unsigned*)(smem + SMMISC) = fb0;
    }

    // resident W_hh tiles
#pragma unroll
    for (int i = 0; i < 32; ++i) {
        int v = i * 256 + tid;
        int split = v >> 12;
        int rem = v & 4095;
        int chunk = rem >> 9;
        int rr = rem & 511;
        int row = rr >> 3, g16 = rr & 7;
        const __nv_bfloat16* src = (split ? whh_l : whh_h);
        uint32_t dst = sb + SMB + split * SMB_SPLIT + chunk * SMB_CHUNK
                     + row * 128 + (uint32_t)((g16 * 16) ^ ((row & 7) * 16));
        cp16(dst, src + (size_t)(bn + row) * HH + chunk * 64 + g16 * 8);
    }
    CP_COMMIT();

    auto sts4 = [&](uint32_t base, int row, int lc, uint32_t val) {
        uint32_t bc = (uint32_t)(lc * 2);
        uint32_t off = (uint32_t)(row * 128)
                     + ((bc & ~15u) ^ (((uint32_t)(row & 7)) << 4)) + (bc & 15u);
        *(uint32_t*)(smem + base + off) = val;
    };
    const uint32_t selfA = (uint32_t)(SMA + ntile * SMA_CHUNK);

    // step 0: h1 = tanh(xp_0)
#pragma unroll
    for (int i = 0; i < 2; ++i) {
        int v = i * 256 + tid;
        int row = v >> 4, c4 = v & 15;
        const float4 x = *(const float4*)(xp + (bm + row) * HH + bn + c4 * 4);
        float v0 = fast_tanh(x.x), v1 = fast_tanh(x.y);
        float v2 = fast_tanh(x.z), v3 = fast_tanh(x.w);
        __nv_bfloat16 h0, l0, h1, l1, h2, l2, h3, l3;
        split1(v0, h0, l0); split1(v1, h1, l1);
        split1(v2, h2, l2); split1(v3, h3, l3);
        __nv_bfloat162 hp0(h0, h1), hp1(h2, h3), lp0(l0, l1), lp1(l2, l3);
        size_t off = (bm + row) * HH + bn + c4 * 4;
        *(uint2*)(hhi + off) = make_uint2(*(uint32_t*)&hp0, *(uint32_t*)&hp1);
        *(uint2*)(hlo + off) = make_uint2(*(uint32_t*)&lp0, *(uint32_t*)&lp1);
        sts4(selfA, row, c4 * 4, *(uint32_t*)&hp0);
        sts4(selfA, row, c4 * 4 + 2, *(uint32_t*)&hp1);
        sts4(selfA + 4096, row, c4 * 4, *(uint32_t*)&lp0);
        sts4(selfA + 4096, row, c4 * 4 + 2, *(uint32_t*)&lp1);
    }
    CP_WAIT(0);
    __syncthreads();
    const unsigned fb = *(const unsigned*)(smem + SMMISC);
    if (tid == 0)
        asm volatile("red.release.gpu.global.add.u32 [%0], %1;"
                     :: "l"(&g_flag[mtile][ntile * 32]), "r"(1u) : "memory");

    const int sub = lane >> 3, li = lane & 7;
    const int arow = (sub & 1) * 8 + li;
    const int akb  = (sub >> 1) * 16;
    const int brow = (sub >> 1) * 8 + li;
    const int bkb  = (sub & 1) * 16;
    const uint32_t swx = (uint32_t)(li * 16);
    const int g = lane >> 2, tg = lane & 3;

    for (int t = 1; t < TT; ++t) {
        const __nv_bfloat16* Ah = hhi;
        const __nv_bfloat16* Al = hlo;
        const float* xpt = xp + (size_t)t * BH;

        float acc[2][4];
#pragma unroll
        for (int ni = 0; ni < 2; ++ni)
#pragma unroll
            for (int q = 0; q < 4; ++q) acc[ni][q] = 0.0f;

        auto compute_chunk = [&](int c) {
            const uint32_t aHi = sb + SMA + c * SMA_CHUNK + (uint32_t)((wm + arow) * 128);
            const uint32_t aLo = aHi + 4096;
            const uint32_t bHi = sb + SMB + c * SMB_CHUNK + (uint32_t)((wn + brow) * 128);
            const uint32_t bLo = bHi + SMB_SPLIT;
#pragma unroll
            for (int kk = 0; kk < 4; ++kk) {
                const uint32_t ka  = (uint32_t)(kk * 32 + akb) ^ swx;
                const uint32_t kb2 = (uint32_t)(kk * 32 + bkb) ^ swx;
                uint32_t ah[4], al4[4], bh[4], bl[4];
                ldsm4(ah, aHi + ka);
                ldsm4(al4, aLo + ka);
                ldsm4(bh, bHi + kb2);
                ldsm4(bl, bLo + kb2);
#pragma unroll
                for (int ni = 0; ni < 2; ++ni)
                    mma16816(acc[ni], ah, bh[2 * ni], bh[2 * ni + 1]);
#pragma unroll
                for (int ni = 0; ni < 2; ++ni)
                    mma16816(acc[ni], ah, bl[2 * ni], bl[2 * ni + 1]);
#pragma unroll
                for (int ni = 0; ni < 2; ++ni)
                    mma16816(acc[ni], al4, bh[2 * ni], bh[2 * ni + 1]);
            }
        };

        // phase -1: issue xp load (depends on nothing; group 1)
        {
#pragma unroll
            for (int i = 0; i < 2; ++i) {
                int v = i * 256 + tid;
                int row = v >> 4, g16 = v & 15;
                cp16(sb + SMXP + row * 256 + g16 * 16,
                     xpt + (bm + row) * HH + bn + g16 * 4);
            }
            CP_COMMIT();
        }

        // phase 0: self chunk (A already in smem from previous epilogue)
        compute_chunk(ntile);

        // phase 1: wait for the 7 peer producers of h_t
        if (tid < 7) {
            const int c = (ntile + 1 + tid) & 7;
            const unsigned* fl = &g_flag[mtile][c * 32];
            const unsigned target = fb + (unsigned)t;
            unsigned v;
            do {
                asm volatile("ld.acquire.gpu.global.u32 %0, [%1];" : "=r"(v) : "l"(fl));
            } while ((int)(v - target) < 0);
        }
        __syncthreads();

        // phase 2: issue peer chunk loads (groups 2..8)
#pragma unroll
        for (int j = 1; j < 8; ++j) {
            const int c = (ntile + j) & 7;
            const uint32_t base = sb + SMA + c * SMA_CHUNK;
#pragma unroll
            for (int i = 0; i < 2; ++i) {
                int v = i * 256 + tid;
                int split = v >> 8;
                int rr = v & 255;
                int row = rr >> 3, g16 = rr & 7;
                const __nv_bfloat16* src = (split ? Al : Ah);
                uint32_t dst = base + split * 4096 + row * 128
                             + (uint32_t)((g16 * 16) ^ ((row & 7) * 16));
                cp16(dst, src + (bm + (size_t)row) * HH + c * 64 + g16 * 8);
            }
            CP_COMMIT();
        }

        // phase 3: staged waits + peer chunk computes
#pragma unroll
        for (int j = 1; j < 8; j += 2) {
            if (j == 1)      { CP_WAIT(5); }
            else if (j == 3) { CP_WAIT(3); }
            else if (j == 5) { CP_WAIT(1); }
            else             { CP_WAIT(0); }
            __syncthreads();
            compute_chunk((ntile + j) & 7);
            if (j + 1 < 8) compute_chunk((ntile + j + 1) & 7);
        }

        // phase 4: epilogue
        const float* sXP = (const float*)(smem + SMXP);
#pragma unroll
        for (int ni = 0; ni < 2; ++ni) {
            const int lr0 = wm + g;
            const int lc  = wn + ni * 8 + 2 * tg;
            const size_t r0 = bm + (size_t)lr0;
            const size_t r1 = r0 + 8;
            const int c0 = bn + lc;
            float2 x0 = *(const float2*)(sXP + lr0 * PBN + lc);
            float2 x1 = *(const float2*)(sXP + (lr0 + 8) * PBN + lc);
            float v0 = fast_tanh(acc[0][0] * 0.0f + acc[ni][0] + x0.x);
            float v1 = fast_tanh(acc[ni][1] + x0.y);
            float v2 = fast_tanh(acc[ni][2] + x1.x);
            float v3 = fast_tanh(acc[ni][3] + x1.y);
            if (t == TT - 1) {
                *(float2*)(out + r0 * HH + c0) = make_float2(v0, v1);
                *(float2*)(out + r1 * HH + c0) = make_float2(v2, v3);
            } else {
                __nv_bfloat16 h0, l0, h1, l1, h2, l2, h3, l3;
                split1(v0, h0, l0); split1(v1, h1, l1);
                split1(v2, h2, l2); split1(v3, h3, l3);
                __nv_bfloat162 hp0(h0, h1), hp1(h2, h3), lp0(l0, l1), lp1(l2, l3);
                *(uint32_t*)(hhi + r0 * HH + c0) = *(uint32_t*)&hp0;
                *(uint32_t*)(hlo + r0 * HH + c0) = *(uint32_t*)&lp0;
                *(uint32_t*)(hhi + r1 * HH + c0) = *(uint32_t*)&hp1;
                *(uint32_t*)(hlo + r1 * HH + c0) = *(uint32_t*)&lp1;
                sts4(selfA, lr0, lc, *(uint32_t*)&hp0);
                sts4(selfA + 4096, lr0, lc, *(uint32_t*)&lp0);
                sts4(selfA, lr0 + 8, lc, *(uint32_t*)&hp1);
                sts4(selfA + 4096, lr0 + 8, lc, *(uint32_t*)&lp1);
            }
        }

        __syncthreads();
        if (tid == 0 && t < TT - 1)
            asm volatile("red.release.gpu.global.add.u32 [%0], %1;"
                         :: "l"(&g_flag[mtile][ntile * 32]), "r"(1u) : "memory");
    }
}

// -------------------- launcher ---------------------------------------------
extern "C" void kernel_launch(void* const* d_in, const int* in_sizes, int n_in,
                              void* d_out, int out_size)
{
    const float* X   = (const float*)d_in[0];
    const float* Wih = (const float*)d_in[1];
    const float* Whh = (const float*)d_in[2];
    const float* bih = (const float*)d_in[3];
    const float* bhh = (const float*)d_in[4];
    float* out = (float*)d_out;

    float* xp;
    __nv_bfloat16 *xhi, *xlo, *wih_h, *wih_l, *whh_h, *whh_l, *hhi, *hlo;
    cudaGetSymbolAddress((void**)&xp, g_xp);
    cudaGetSymbolAddress((void**)&xhi, g_xhi);
    cudaGetSymbolAddress((void**)&xlo, g_xlo);
    cudaGetSymbolAddress((void**)&wih_h, g_wih_h);
    cudaGetSymbolAddress((void**)&wih_l, g_wih_l);
    cudaGetSymbolAddress((void**)&whh_h, g_whh_h);
    cudaGetSymbolAddress((void**)&whh_l, g_whh_l);
    cudaGetSymbolAddress((void**)&hhi, g_hhi);
    cudaGetSymbolAddress((void**)&hlo, g_hlo);

    // xp kernel: BM=64, BN=128 -> STAGE = 2*8K + 2*16K = 48K; x2 stages = 96K
    constexpr int SMEM_XP = 2 * (2 * 64 * 128 + 2 * 128 * 128);  // 98304
    cudaFuncSetAttribute(gemm_split_kernel<64, 128, 32, 32>,
                         cudaFuncAttributeMaxDynamicSharedMemorySize, SMEM_XP);
    cudaFuncSetAttribute(rnn_persistent_kernel,
                         cudaFuncAttributeMaxDynamicSharedMemorySize, PSMEM);

    // 1) hi/lo splits
    split_kernel<<<128, 256>>>(Wih, wih_h, wih_l, HH * DD / 4);
    split_kernel<<<128, 256>>>(Whh, whh_h, whh_l, HH * HH / 4);
    split_kernel<<<8192, 256>>>(X, xhi, xlo, (int)((size_t)TT * BB * DD / 4));

    // 2) xp = X @ Wih^T + (b_ih + b_hh)
    {
        dim3 g(HH / 128, (TT * BB) / 64);  // (4, 4096)
        gemm_split_kernel<64, 128, 32, 32><<<g, 256, SMEM_XP>>>(
            xhi, xlo, wih_h, wih_l, bih, bhh, xp);
    }

    // 3) entire recurrence in one persistent kernel
    rnn_persistent_kernel<<<NCTA, 256, PSMEM>>>(xp, whh_h, whh_l, hhi, hlo, out);
}

// round 10
// speedup vs baseline: 1.7571x; 1.0832x over previous
#include <cuda_runtime.h>
#include <cuda_bf16.h>
#include <math.h>
#include <stdint.h>

// Problem dims (fixed)
#define TT 512
#define BB 512
#define DD 512
#define HH 512
#define BH (BB * HH)  // 262144

// -------------------- device scratch (no allocations allowed) --------------
__device__ float          g_xp[(size_t)TT * BH];            // 512 MB
__device__ __nv_bfloat16  g_xhi[(size_t)TT * BB * DD];      // 256 MB
__device__ __nv_bfloat16  g_xlo[(size_t)TT * BB * DD];      // 256 MB
__device__ __nv_bfloat16  g_wih_h[HH * DD], g_wih_l[HH * DD];
__device__ __nv_bfloat16  g_whh_h[HH * HH], g_whh_l[HH * HH];
__device__ __nv_bfloat16  g_hhi[2][BH], g_hlo[2][BH];

// producer flags: flag[rg][n*32], rg = 0..31 (16-row groups), n = 0..7.
// Monotonic; every owner increments exactly 511 times per launch.
__device__ unsigned g_flag[32][8 * 32];

// -------------------- PTX helpers (sm_80-level only; no 'a' features) ------
__device__ __forceinline__ uint32_t smem_u32(const void* p) {
    uint32_t a;
    asm("{ .reg .u64 t; cvta.to.shared.u64 t, %1; cvt.u32.u64 %0, t; }" : "=r"(a) : "l"(p));
    return a;
}
__device__ __forceinline__ void cp16(uint32_t s, const void* g) {
    asm volatile("cp.async.cg.shared.global [%0], [%1], 16;" :: "r"(s), "l"(g));
}
#define CP_COMMIT() asm volatile("cp.async.commit_group;" ::: "memory")
#define CP_WAIT(n)  asm volatile("cp.async.wait_group %0;" :: "n"(n) : "memory")
#define BARH(id)    asm volatile("bar.sync %0, 128;" :: "r"(id) : "memory")

__device__ __forceinline__ void ldsm4(uint32_t* r, uint32_t addr) {
    asm volatile("ldmatrix.sync.aligned.m8n8.x4.shared.b16 {%0,%1,%2,%3}, [%4];"
                 : "=r"(r[0]), "=r"(r[1]), "=r"(r[2]), "=r"(r[3]) : "r"(addr));
}
__device__ __forceinline__ void mma16816(float* d, const uint32_t* a, uint32_t b0, uint32_t b1) {
    asm volatile("mma.sync.aligned.m16n8k16.row.col.f32.bf16.bf16.f32 "
                 "{%0,%1,%2,%3}, {%4,%5,%6,%7}, {%8,%9}, {%0,%1,%2,%3};"
                 : "+f"(d[0]), "+f"(d[1]), "+f"(d[2]), "+f"(d[3])
                 : "r"(a[0]), "r"(a[1]), "r"(a[2]), "r"(a[3]), "r"(b0), "r"(b1));
}

// fast tanh: 1 - 2/(e^{2x}+1) via MUFU (abs err ~1e-6; saturates correctly)
__device__ __forceinline__ float fast_tanh(float x) {
    float e = __expf(2.0f * x);
    return 1.0f - __fdividef(2.0f, e + 1.0f);
}

// -------------------- split helpers ----------------------------------------
__device__ __forceinline__ void split1(float x, __nv_bfloat16& h, __nv_bfloat16& l) {
    h = __float2bfloat16_rn(x);
    l = __float2bfloat16_rn(x - __bfloat162float(h));
}

__global__ __launch_bounds__(256) void split_kernel(const float* __restrict__ src,
                                                    __nv_bfloat16* __restrict__ hi,
                                                    __nv_bfloat16* __restrict__ lo, int n4) {
    for (int i = blockIdx.x * blockDim.x + threadIdx.x; i < n4; i += gridDim.x * blockDim.x) {
        float4 v = ((const float4*)src)[i];
        __nv_bfloat16 h0, h1, h2, h3, l0, l1, l2, l3;
        split1(v.x, h0, l0); split1(v.y, h1, l1);
        split1(v.z, h2, l2); split1(v.w, h3, l3);
        __nv_bfloat162* ph = (__nv_bfloat162*)hi;
        __nv_bfloat162* pl = (__nv_bfloat162*)lo;
        ph[i * 2] = __nv_bfloat162(h0, h1); ph[i * 2 + 1] = __nv_bfloat162(h2, h3);
        pl[i * 2] = __nv_bfloat162(l0, l1); pl[i * 2 + 1] = __nv_bfloat162(l2, l3);
    }
}

// -------------------- async tile loader (64-col bf16 tiles) ----------------
template <int ROWS, int THREADS>
__device__ __forceinline__ void load_tile_async(const __nv_bfloat16* __restrict__ g,
                                                size_t row0, int kbase,
                                                uint32_t sdst, int tid) {
    constexpr int TOT = ROWS * 8;  // 16B granules
#pragma unroll
    for (int i = 0; i < TOT / THREADS; ++i) {
        int v = i * THREADS + tid;
        int row = v >> 3, g16 = v & 7;
        uint32_t off = (uint32_t)(row * 128 + ((g16 * 16) ^ ((row & 7) * 16)));
        cp16(sdst + off, g + (row0 + (size_t)row) * HH + kbase + g16 * 8);
    }
}

// -------------------- xp GEMM (proven round-8 config) ----------------------
template <int BM, int BN, int WM, int WN>
__global__ void __launch_bounds__((BM / WM) * (BN / WN) * 32, 2)
gemm_split_kernel(const __nv_bfloat16* __restrict__ Ahi, const __nv_bfloat16* __restrict__ Alo,
                  const __nv_bfloat16* __restrict__ Bhi, const __nv_bfloat16* __restrict__ Blo,
                  const float* __restrict__ bih, const float* __restrict__ bhh,
                  float* __restrict__ out_f)
{
    constexpr int THREADS = (BM / WM) * (BN / WN) * 32;
    constexpr int SA = BM * 128;
    constexpr int SB = BN * 128;
    constexpr int STAGE = 2 * SA + 2 * SB;
    constexpr int NCHUNK = HH / 64;

    extern __shared__ char smem[];
    const uint32_t sbase = smem_u32(smem);
    const int tid = threadIdx.x;
    const int wid = tid >> 5, lane = tid & 31;
    const size_t bm = (size_t)blockIdx.y * BM;
    const int bn = blockIdx.x * BN;
    const int wm = (wid % (BM / WM)) * WM;
    const int wn = (wid / (BM / WM)) * WN;

    float acc[WM / 16][WN / 8][4];
#pragma unroll
    for (int mi = 0; mi < WM / 16; ++mi)
#pragma unroll
        for (int ni = 0; ni < WN / 8; ++ni)
#pragma unroll
            for (int q = 0; q < 4; ++q) acc[mi][ni][q] = 0.0f;

    const int sub = lane >> 3, li = lane & 7;
    const int arow = (sub & 1) * 8 + li;
    const int akb  = (sub >> 1) * 16;
    const int brow = (sub >> 1) * 8 + li;
    const int bkb  = (sub & 1) * 16;
    const uint32_t swx = (uint32_t)(li * 16);

    auto issue_loads = [&](int c, int s) {
        const uint32_t st = sbase + (uint32_t)(s * STAGE);
        const int kb = c * 64;
        load_tile_async<BM, THREADS>(Ahi, bm, kb, st, tid);
        load_tile_async<BM, THREADS>(Alo, bm, kb, st + SA, tid);
        load_tile_async<BN, THREADS>(Bhi, (size_t)bn, kb, st + 2 * SA, tid);
        load_tile_async<BN, THREADS>(Blo, (size_t)bn, kb, st + 2 * SA + SB, tid);
        CP_COMMIT();
    };

    issue_loads(0, 0);

    for (int c = 0; c < NCHUNK; ++c) {
        if (c + 1 < NCHUNK) {
            issue_loads(c + 1, (c + 1) & 1);
            CP_WAIT(1);
        } else {
            CP_WAIT(0);
        }
        __syncthreads();

        const uint32_t st = sbase + (uint32_t)((c & 1) * STAGE);
        const uint32_t aHi = st + (uint32_t)((wm + arow) * 128);
        const uint32_t aLo = aHi + SA;
        const uint32_t bHi = st + 2 * SA + (uint32_t)((wn + brow) * 128);
        const uint32_t bLo = bHi + SB;

#pragma unroll
        for (int kk = 0; kk < 4; ++kk) {
            const uint32_t ka = (uint32_t)(kk * 32 + akb) ^ swx;
            const uint32_t kb2 = (uint32_t)(kk * 32 + bkb) ^ swx;
            uint32_t ah[WM / 16][4], al[WM / 16][4], bh[WN / 16][4], bl[WN / 16][4];
#pragma unroll
            for (int mi = 0; mi < WM / 16; ++mi) {
                ldsm4(ah[mi], aHi + mi * 2048 + ka);
                ldsm4(al[mi], aLo + mi * 2048 + ka);
            }
#pragma unroll
            for (int nj = 0; nj < WN / 16; ++nj) {
                ldsm4(bh[nj], bHi + nj * 2048 + kb2);
                ldsm4(bl[nj], bLo + nj * 2048 + kb2);
            }
#pragma unroll
            for (int mi = 0; mi < WM / 16; ++mi)
#pragma unroll
                for (int ni = 0; ni < WN / 8; ++ni)
                    mma16816(acc[mi][ni], ah[mi],
                             bh[ni >> 1][2 * (ni & 1)], bh[ni >> 1][2 * (ni & 1) + 1]);
#pragma unroll
            for (int mi = 0; mi < WM / 16; ++mi)
#pragma unroll
                for (int ni = 0; ni < WN / 8; ++ni)
                    mma16816(acc[mi][ni], ah[mi],
                             bl[ni >> 1][2 * (ni & 1)], bl[ni >> 1][2 * (ni & 1) + 1]);
#pragma unroll
            for (int mi = 0; mi < WM / 16; ++mi)
#pragma unroll
                for (int ni = 0; ni < WN / 8; ++ni)
                    mma16816(acc[mi][ni], al[mi],
                             bh[ni >> 1][2 * (ni & 1)], bh[ni >> 1][2 * (ni & 1) + 1]);
        }
        __syncthreads();
    }

    const int g = lane >> 2, tg = lane & 3;
#pragma unroll
    for (int mi = 0; mi < WM / 16; ++mi) {
#pragma unroll
        for (int ni = 0; ni < WN / 8; ++ni) {
            const size_t r0 = bm + (size_t)(wm + mi * 16 + g);
            const size_t r1 = r0 + 8;
            const int c0 = bn + wn + ni * 8 + 2 * tg;
            float b0 = bih[c0] + bhh[c0];
            float b1 = bih[c0 + 1] + bhh[c0 + 1];
            *(float2*)(out_f + r0 * HH + c0) =
                make_float2(acc[mi][ni][0] + b0, acc[mi][ni][1] + b1);
            *(float2*)(out_f + r1 * HH + c0) =
                make_float2(acc[mi][ni][2] + b0, acc[mi][ni][3] + b1);
        }
    }
}

// -------------------- persistent recurrence kernel -------------------------
// 128 CTAs x 256 threads; each CTA = TWO independent 128-thread halves.
// Half h owns tile (rowgroup gidx+16h, ntile): 16 rows x 64 cols. Both halves
// share the resident W_hh slice; each runs its own poll/load/compute/epilogue
// on named barrier (1+half). One warp per half per SMSP -> mutual latency hiding.
#define NCTA 128
#define SMB 0                 // W_hh: hi [0,64K), lo [64K,128K); chunk stride 8K
#define SMB_SPLIT 65536
#define SMB_CHUNK 8192
#define SMA 131072            // A: + half*32768 + chunk*4096 (hi +0, lo +2048)
#define SMA_HALF 32768
#define SMA_CHUNK 4096
#define SMXP 196608           // xp: + half*4096 (16x64 f32)
#define SMMISC 204800
#define PSMEM 204928

__global__ void __launch_bounds__(256, 1)
rnn_persistent_kernel(const float* __restrict__ xp,
                      const __nv_bfloat16* __restrict__ whh_h,
                      const __nv_bfloat16* __restrict__ whh_l,
                      __nv_bfloat16* __restrict__ hhi_base,
                      __nv_bfloat16* __restrict__ hlo_base,
                      float* __restrict__ out)
{
    extern __shared__ char smem[];
    const uint32_t sb = smem_u32(smem);
    const int tid = threadIdx.x;
    const int half = tid >> 7;
    const int htid = tid & 127;
    const int lane = tid & 31;
    const int gidx = blockIdx.x >> 3;       // 0..15
    const int ntile = blockIdx.x & 7;       // 0..7
    const int rg = gidx + half * 16;        // rowgroup 0..31
    const size_t bm = (size_t)rg * 16;      // global row base (16 rows)
    const int bn = ntile * 64;
    const int wn = (htid >> 5) * 16;        // 4 warps/half, WN=16
    const int barid = 1 + half;

    // OFFSETS (for generic-pointer smem stores) vs ADDRESSES (for ldsm/cp.async)
    const uint32_t aOff  = (uint32_t)(SMA + half * SMA_HALF);
    const uint32_t aAddr = sb + aOff;
    const uint32_t selfOff = aOff + (uint32_t)(ntile * SMA_CHUNK);  // sts4 (offset)
    const uint32_t xpAddr  = sb + (uint32_t)(SMXP + half * 4096);   // cp.async dst

    if (htid == 0) {
        unsigned fb0;
        asm volatile("ld.volatile.global.u32 %0, [%1];"
                     : "=r"(fb0) : "l"(&g_flag[rg][ntile * 32]));
        *(unsigned*)(smem + SMMISC + half * 4) = fb0;
    }

    // ---- resident W_hh tiles (rows bn..bn+64, all K), both splits (full CTA)
#pragma unroll
    for (int i = 0; i < 32; ++i) {
        int v = i * 256 + tid;              // 8192 granules
        int split = v >> 12;
        int rem = v & 4095;
        int chunk = rem >> 9;
        int rr = rem & 511;
        int row = rr >> 3, gq = rr & 7;
        const __nv_bfloat16* src = (split ? whh_l : whh_h);
        uint32_t dst = sb + SMB + split * SMB_SPLIT + chunk * SMB_CHUNK
                     + row * 128 + (uint32_t)((gq * 16) ^ ((row & 7) * 16));
        cp16(dst, src + (size_t)(bn + row) * HH + chunk * 64 + gq * 8);
    }
    CP_COMMIT();

    // generic-pointer smem store of a 4B pair at (row, even col lc), swizzled.
    // base is an OFFSET from smem[0].
    auto sts4 = [&](uint32_t base, int row, int lc, uint32_t val) {
        uint32_t bc = (uint32_t)(lc * 2);
        uint32_t off = (uint32_t)(row * 128)
                     + ((bc & ~15u) ^ (((uint32_t)(row & 7)) << 4)) + (bc & 15u);
        *(uint32_t*)(smem + base + off) = val;
    };

    // ---- step 0: h1 = tanh(xp_0) -> buf 0 + self smem chunk ---------------
#pragma unroll
    for (int i = 0; i < 2; ++i) {
        int v = i * 128 + htid;             // 256 float4 granules (16 rows x 16)
        int row = v >> 4, c4 = v & 15;
        const float4 x = *(const float4*)(xp + (bm + row) * HH + bn + c4 * 4);
        float v0 = fast_tanh(x.x), v1 = fast_tanh(x.y);
        float v2 = fast_tanh(x.z), v3 = fast_tanh(x.w);
        __nv_bfloat16 h0, l0, h1, l1, h2, l2, h3, l3;
        split1(v0, h0, l0); split1(v1, h1, l1);
        split1(v2, h2, l2); split1(v3, h3, l3);
        __nv_bfloat162 hp0(h0, h1), hp1(h2, h3), lp0(l0, l1), lp1(l2, l3);
        size_t off = (bm + row) * HH + bn + c4 * 4;
        *(uint2*)(hhi_base + off) = make_uint2(*(uint32_t*)&hp0, *(uint32_t*)&hp1);
        *(uint2*)(hlo_base + off) = make_uint2(*(uint32_t*)&lp0, *(uint32_t*)&lp1);
        sts4(selfOff, row, c4 * 4, *(uint32_t*)&hp0);
        sts4(selfOff, row, c4 * 4 + 2, *(uint32_t*)&hp1);
        sts4(selfOff + 2048, row, c4 * 4, *(uint32_t*)&lp0);
        sts4(selfOff + 2048, row, c4 * 4 + 2, *(uint32_t*)&lp1);
    }
    CP_WAIT(0);
    __syncthreads();                         // last full-CTA barrier
    const unsigned fb = *(const unsigned*)(smem + SMMISC + half * 4);
    if (htid == 0)
        asm volatile("red.release.gpu.global.add.u32 [%0], %1;"
                     :: "l"(&g_flag[rg][ntile * 32]), "r"(1u) : "memory");

    // ldmatrix lane geometry (16-row A tiles)
    const int sub = lane >> 3, li = lane & 7;
    const int arow = (sub & 1) * 8 + li;
    const int akb  = (sub >> 1) * 16;
    const int brow = (sub >> 1) * 8 + li;
    const int bkb  = (sub & 1) * 16;
    const uint32_t swx = (uint32_t)(li * 16);
    const int gl = lane >> 2, tg = lane & 3;

    for (int t = 1; t < TT; ++t) {
        const __nv_bfloat16* Ah = hhi_base + (size_t)((t - 1) & 1) * BH;
        const __nv_bfloat16* Al = hlo_base + (size_t)((t - 1) & 1) * BH;
        __nv_bfloat16* Oh = hhi_base + (size_t)(t & 1) * BH;
        __nv_bfloat16* Ol = hlo_base + (size_t)(t & 1) * BH;
        const float* xpt = xp + (size_t)t * BH;

        float acc[2][4];
#pragma unroll
        for (int ni = 0; ni < 2; ++ni)
#pragma unroll
            for (int q = 0; q < 4; ++q) acc[ni][q] = 0.0f;

        auto compute_chunk = [&](int c) {
            const uint32_t aHi = aAddr + c * SMA_CHUNK + (uint32_t)(arow * 128);
            const uint32_t aLo = aHi + 2048;
            const uint32_t bHi = sb + SMB + c * SMB_CHUNK + (uint32_t)((wn + brow) * 128);
            const uint32_t bLo = bHi + SMB_SPLIT;
#pragma unroll
            for (int kk = 0; kk < 4; ++kk) {
                const uint32_t ka  = (uint32_t)(kk * 32 + akb) ^ swx;
                const uint32_t kb2 = (uint32_t)(kk * 32 + bkb) ^ swx;
                uint32_t ah[4], al4[4], bh[4], bl[4];
                ldsm4(ah, aHi + ka);
                ldsm4(al4, aLo + ka);
                ldsm4(bh, bHi + kb2);
                ldsm4(bl, bLo + kb2);
#pragma unroll
                for (int ni = 0; ni < 2; ++ni)
                    mma16816(acc[ni], ah, bh[2 * ni], bh[2 * ni + 1]);
#pragma unroll
                for (int ni = 0; ni < 2; ++ni)
                    mma16816(acc[ni], ah, bl[2 * ni], bl[2 * ni + 1]);
#pragma unroll
                for (int ni = 0; ni < 2; ++ni)
                    mma16816(acc[ni], al4, bh[2 * ni], bh[2 * ni + 1]);
            }
        };

        // phase -1: issue xp tile load (group 1)
        {
#pragma unroll
            for (int i = 0; i < 2; ++i) {
                int v = i * 128 + htid;      // 256 granules (16 rows x 16)
                int row = v >> 4, gq = v & 15;
                cp16(xpAddr + row * 256 + gq * 16,
                     xpt + (bm + row) * HH + bn + gq * 4);
            }
            CP_COMMIT();
        }

        // phase 0: self chunk (A in smem from own previous epilogue)
        compute_chunk(ntile);

        // phase 1: poll the 7 peer producers of rowgroup rg
        if (htid < 7) {
            const int c = (ntile + 1 + htid) & 7;
            const unsigned* fl = &g_flag[rg][c * 32];
            const unsigned target = fb + (unsigned)t;
            unsigned v;
            do {
                asm volatile("ld.acquire.gpu.global.u32 %0, [%1];" : "=r"(v) : "l"(fl));
            } while ((int)(v - target) < 0);
        }
        BARH(barid);

        // phase 2: issue peer chunk loads (7 groups)
#pragma unroll
        for (int j = 1; j < 8; ++j) {
            const int c = (ntile + j) & 7;
            const uint32_t base = aAddr + c * SMA_CHUNK;
#pragma unroll
            for (int i = 0; i < 2; ++i) {
                int v = i * 128 + htid;      // 256 granules (hi 128 + lo 128)
                int split = v >> 7;
                int rr = v & 127;
                int row = rr >> 3, gq = rr & 7;
                const __nv_bfloat16* src = (split ? Al : Ah);
                uint32_t dst = base + split * 2048 + row * 128
                             + (uint32_t)((gq * 16) ^ ((row & 7) * 16));
                cp16(dst, src + (bm + (size_t)row) * HH + c * 64 + gq * 8);
            }
            CP_COMMIT();
        }

        // phase 3: staged waits + peer chunk computes
#pragma unroll
        for (int j = 1; j < 8; j += 2) {
            if (j == 1)      { CP_WAIT(5); }
            else if (j == 3) { CP_WAIT(3); }
            else if (j == 5) { CP_WAIT(1); }
            else             { CP_WAIT(0); }
            BARH(barid);
            compute_chunk((ntile + j) & 7);
            if (j + 1 < 8) compute_chunk((ntile + j + 1) & 7);
        }

        // phase 4: epilogue — tanh(acc + xp); write h (or final out)
        const float* sXP = (const float*)(smem + SMXP + half * 4096);
#pragma unroll
        for (int ni = 0; ni < 2; ++ni) {
            const int lr0 = gl;              // rows 0..7 and +8
            const int lc  = wn + ni * 8 + 2 * tg;
            const size_t r0 = bm + (size_t)lr0;
            const size_t r1 = r0 + 8;
            const int c0 = bn + lc;
            float2 x0 = *(const float2*)(sXP + lr0 * 64 + lc);
            float2 x1 = *(const float2*)(sXP + (lr0 + 8) * 64 + lc);
            float v0 = fast_tanh(acc[ni][0] + x0.x);
            float v1 = fast_tanh(acc[ni][1] + x0.y);
            float v2 = fast_tanh(acc[ni][2] + x1.x);
            float v3 = fast_tanh(acc[ni][3] + x1.y);
            if (t == TT - 1) {
                *(float2*)(out + r0 * HH + c0) = make_float2(v0, v1);
                *(float2*)(out + r1 * HH + c0) = make_float2(v2, v3);
            } else {
                __nv_bfloat16 h0, l0, h1, l1, h2, l2, h3, l3;
                split1(v0, h0, l0); split1(v1, h1, l1);
                split1(v2, h2, l2); split1(v3, h3, l3);
                __nv_bfloat162 hp0(h0, h1), hp1(h2, h3), lp0(l0, l1), lp1(l2, l3);
                *(uint32_t*)(Oh + r0 * HH + c0) = *(uint32_t*)&hp0;
                *(uint32_t*)(Ol + r0 * HH + c0) = *(uint32_t*)&lp0;
                *(uint32_t*)(Oh + r1 * HH + c0) = *(uint32_t*)&hp1;
                *(uint32_t*)(Ol + r1 * HH + c0) = *(uint32_t*)&lp1;
                sts4(selfOff, lr0, lc, *(uint32_t*)&hp0);
                sts4(selfOff + 2048, lr0, lc, *(uint32_t*)&lp0);
                sts4(selfOff, lr0 + 8, lc, *(uint32_t*)&hp1);
                sts4(selfOff + 2048, lr0 + 8, lc, *(uint32_t*)&lp1);
            }
        }

        BARH(barid);   // all of this half's STG/STS done
        if (htid == 0 && t < TT - 1)
            asm volatile("red.release.gpu.global.add.u32 [%0], %1;"
                         :: "l"(&g_flag[rg][ntile * 32]), "r"(1u) : "memory");
    }
}

// -------------------- launcher ---------------------------------------------
extern "C" void kernel_launch(void* const* d_in, const int* in_sizes, int n_in,
                              void* d_out, int out_size)
{
    const float* X   = (const float*)d_in[0];
    const float* Wih = (const float*)d_in[1];
    const float* Whh = (const float*)d_in[2];
    const float* bih = (const float*)d_in[3];
    const float* bhh = (const float*)d_in[4];
    float* out = (float*)d_out;

    float* xp;
    __nv_bfloat16 *xhi, *xlo, *wih_h, *wih_l, *whh_h, *whh_l, *hhi, *hlo;
    cudaGetSymbolAddress((void**)&xp, g_xp);
    cudaGetSymbolAddress((void**)&xhi, g_xhi);
    cudaGetSymbolAddress((void**)&xlo, g_xlo);
    cudaGetSymbolAddress((void**)&wih_h, g_wih_h);
    cudaGetSymbolAddress((void**)&wih_l, g_wih_l);
    cudaGetSymbolAddress((void**)&whh_h, g_whh_h);
    cudaGetSymbolAddress((void**)&whh_l, g_whh_l);
    cudaGetSymbolAddress((void**)&hhi, g_hhi);
    cudaGetSymbolAddress((void**)&hlo, g_hlo);

    constexpr int SMEM_XP = 2 * (2 * 64 * 128 + 2 * 128 * 128);  // 98304
    cudaFuncSetAttribute(gemm_split_kernel<64, 128, 32, 32>,
                         cudaFuncAttributeMaxDynamicSharedMemorySize, SMEM_XP);
    cudaFuncSetAttribute(rnn_persistent_kernel,
                         cudaFuncAttributeMaxDynamicSharedMemorySize, PSMEM);

    // 1) hi/lo splits
    split_kernel<<<128, 256>>>(Wih, wih_h, wih_l, HH * DD / 4);
    split_kernel<<<128, 256>>>(Whh, whh_h, whh_l, HH * HH / 4);
    split_kernel<<<8192, 256>>>(X, xhi, xlo, (int)((size_t)TT * BB * DD / 4));

    // 2) xp = X @ Wih^T + (b_ih + b_hh)
    {
        dim3 g(HH / 128, (TT * BB) / 64);  // (4, 4096)
        gemm_split_kernel<64, 128, 32, 32><<<g, 256, SMEM_XP>>>(
            xhi, xlo, wih_h, wih_l, bih, bhh, xp);
    }

    // 3) entire recurrence in one persistent kernel (dual half-CTAs)
    rnn_persistent_kernel<<<NCTA, 256, PSMEM>>>(xp, whh_h, whh_l, hhi, hlo, out);
}

// round 11
// speedup vs baseline: 1.8026x; 1.0259x over previous
#include <cuda_runtime.h>
#include <cuda_bf16.h>
#include <math.h>
#include <stdint.h>

// Problem dims (fixed)
#define TT 512
#define BB 512
#define DD 512
#define HH 512
#define BH (BB * HH)  // 262144

// -------------------- device scratch (no allocations allowed) --------------
__device__ float          g_xp[(size_t)TT * BH];            // 512 MB
__device__ __nv_bfloat16  g_xhi[(size_t)TT * BB * DD];      // 256 MB
__device__ __nv_bfloat16  g_xlo[(size_t)TT * BB * DD];      // 256 MB
__device__ __nv_bfloat16  g_wih_h[HH * DD], g_wih_l[HH * DD];
__device__ __nv_bfloat16  g_whh_h[HH * HH], g_whh_l[HH * HH];
__device__ __nv_bfloat16  g_hhi[2][BH], g_hlo[2][BH];

// producer flags: flag[rg][n*32], rg = 0..31 (16-row groups), n = 0..7.
// Monotonic; every owner increments exactly 511 times per launch.
__device__ unsigned g_flag[32][8 * 32];

// -------------------- PTX helpers (sm_80-level only; no 'a' features) ------
__device__ __forceinline__ uint32_t smem_u32(const void* p) {
    uint32_t a;
    asm("{ .reg .u64 t; cvta.to.shared.u64 t, %1; cvt.u32.u64 %0, t; }" : "=r"(a) : "l"(p));
    return a;
}
__device__ __forceinline__ void cp16(uint32_t s, const void* g) {
    asm volatile("cp.async.cg.shared.global [%0], [%1], 16;" :: "r"(s), "l"(g));
}
#define CP_COMMIT() asm volatile("cp.async.commit_group;" ::: "memory")
#define CP_WAIT(n)  asm volatile("cp.async.wait_group %0;" :: "n"(n) : "memory")
#define BARH(id)    asm volatile("bar.sync %0, 128;" :: "r"(id) : "memory")

__device__ __forceinline__ void st_rel_shared(uint32_t addr, unsigned v) {
    asm volatile("st.release.cta.shared.u32 [%0], %1;" :: "r"(addr), "r"(v) : "memory");
}
__device__ __forceinline__ unsigned ld_acq_shared(uint32_t addr) {
    unsigned v;
    asm volatile("ld.acquire.cta.shared.u32 %0, [%1];" : "=r"(v) : "r"(addr) : "memory");
    return v;
}

__device__ __forceinline__ void ldsm4(uint32_t* r, uint32_t addr) {
    asm volatile("ldmatrix.sync.aligned.m8n8.x4.shared.b16 {%0,%1,%2,%3}, [%4];"
                 : "=r"(r[0]), "=r"(r[1]), "=r"(r[2]), "=r"(r[3]) : "r"(addr));
}
__device__ __forceinline__ void mma16816(float* d, const uint32_t* a, uint32_t b0, uint32_t b1) {
    asm volatile("mma.sync.aligned.m16n8k16.row.col.f32.bf16.bf16.f32 "
                 "{%0,%1,%2,%3}, {%4,%5,%6,%7}, {%8,%9}, {%0,%1,%2,%3};"
                 : "+f"(d[0]), "+f"(d[1]), "+f"(d[2]), "+f"(d[3])
                 : "r"(a[0]), "r"(a[1]), "r"(a[2]), "r"(a[3]), "r"(b0), "r"(b1));
}

// fast tanh: 1 - 2/(e^{2x}+1) via MUFU (abs err ~1e-6; saturates correctly)
__device__ __forceinline__ float fast_tanh(float x) {
    float e = __expf(2.0f * x);
    return 1.0f - __fdividef(2.0f, e + 1.0f);
}

// -------------------- split helpers ----------------------------------------
__device__ __forceinline__ void split1(float x, __nv_bfloat16& h, __nv_bfloat16& l) {
    h = __float2bfloat16_rn(x);
    l = __float2bfloat16_rn(x - __bfloat162float(h));
}

__global__ __launch_bounds__(256) void split_kernel(const float* __restrict__ src,
                                                    __nv_bfloat16* __restrict__ hi,
                                                    __nv_bfloat16* __restrict__ lo, int n4) {
    for (int i = blockIdx.x * blockDim.x + threadIdx.x; i < n4; i += gridDim.x * blockDim.x) {
        float4 v = ((const float4*)src)[i];
        __nv_bfloat16 h0, h1, h2, h3, l0, l1, l2, l3;
        split1(v.x, h0, l0); split1(v.y, h1, l1);
        split1(v.z, h2, l2); split1(v.w, h3, l3);
        __nv_bfloat162* ph = (__nv_bfloat162*)hi;
        __nv_bfloat162* pl = (__nv_bfloat162*)lo;
        ph[i * 2] = __nv_bfloat162(h0, h1); ph[i * 2 + 1] = __nv_bfloat162(h2, h3);
        pl[i * 2] = __nv_bfloat162(l0, l1); pl[i * 2 + 1] = __nv_bfloat162(l2, l3);
    }
}

// -------------------- async tile loader (64-col bf16 tiles) ----------------
template <int ROWS, int THREADS>
__device__ __forceinline__ void load_tile_async(const __nv_bfloat16* __restrict__ g,
                                                size_t row0, int kbase,
                                                uint32_t sdst, int tid) {
    constexpr int TOT = ROWS * 8;  // 16B granules
#pragma unroll
    for (int i = 0; i < TOT / THREADS; ++i) {
        int v = i * THREADS + tid;
        int row = v >> 3, g16 = v & 7;
        uint32_t off = (uint32_t)(row * 128 + ((g16 * 16) ^ ((row & 7) * 16)));
        cp16(sdst + off, g + (row0 + (size_t)row) * HH + kbase + g16 * 8);
    }
}

// -------------------- xp GEMM (proven round-8 config) ----------------------
template <int BM, int BN, int WM, int WN>
__global__ void __launch_bounds__((BM / WM) * (BN / WN) * 32, 2)
gemm_split_kernel(const __nv_bfloat16* __restrict__ Ahi, const __nv_bfloat16* __restrict__ Alo,
                  const __nv_bfloat16* __restrict__ Bhi, const __nv_bfloat16* __restrict__ Blo,
                  const float* __restrict__ bih, const float* __restrict__ bhh,
                  float* __restrict__ out_f)
{
    constexpr int THREADS = (BM / WM) * (BN / WN) * 32;
    constexpr int SA = BM * 128;
    constexpr int SB = BN * 128;
    constexpr int STAGE = 2 * SA + 2 * SB;
    constexpr int NCHUNK = HH / 64;

    extern __shared__ char smem[];
    const uint32_t sbase = smem_u32(smem);
    const int tid = threadIdx.x;
    const int wid = tid >> 5, lane = tid & 31;
    const size_t bm = (size_t)blockIdx.y * BM;
    const int bn = blockIdx.x * BN;
    const int wm = (wid % (BM / WM)) * WM;
    const int wn = (wid / (BM / WM)) * WN;

    float acc[WM / 16][WN / 8][4];
#pragma unroll
    for (int mi = 0; mi < WM / 16; ++mi)
#pragma unroll
        for (int ni = 0; ni < WN / 8; ++ni)
#pragma unroll
            for (int q = 0; q < 4; ++q) acc[mi][ni][q] = 0.0f;

    const int sub = lane >> 3, li = lane & 7;
    const int arow = (sub & 1) * 8 + li;
    const int akb  = (sub >> 1) * 16;
    const int brow = (sub >> 1) * 8 + li;
    const int bkb  = (sub & 1) * 16;
    const uint32_t swx = (uint32_t)(li * 16);

    auto issue_loads = [&](int c, int s) {
        const uint32_t st = sbase + (uint32_t)(s * STAGE);
        const int kb = c * 64;
        load_tile_async<BM, THREADS>(Ahi, bm, kb, st, tid);
        load_tile_async<BM, THREADS>(Alo, bm, kb, st + SA, tid);
        load_tile_async<BN, THREADS>(Bhi, (size_t)bn, kb, st + 2 * SA, tid);
        load_tile_async<BN, THREADS>(Blo, (size_t)bn, kb, st + 2 * SA + SB, tid);
        CP_COMMIT();
    };

    issue_loads(0, 0);

    for (int c = 0; c < NCHUNK; ++c) {
        if (c + 1 < NCHUNK) {
            issue_loads(c + 1, (c + 1) & 1);
            CP_WAIT(1);
        } else {
            CP_WAIT(0);
        }
        __syncthreads();

        const uint32_t st = sbase + (uint32_t)((c & 1) * STAGE);
        const uint32_t aHi = st + (uint32_t)((wm + arow) * 128);
        const uint32_t aLo = aHi + SA;
        const uint32_t bHi = st + 2 * SA + (uint32_t)((wn + brow) * 128);
        const uint32_t bLo = bHi + SB;

#pragma unroll
        for (int kk = 0; kk < 4; ++kk) {
            const uint32_t ka = (uint32_t)(kk * 32 + akb) ^ swx;
            const uint32_t kb2 = (uint32_t)(kk * 32 + bkb) ^ swx;
            uint32_t ah[WM / 16][4], al[WM / 16][4], bh[WN / 16][4], bl[WN / 16][4];
#pragma unroll
            for (int mi = 0; mi < WM / 16; ++mi) {
                ldsm4(ah[mi], aHi + mi * 2048 + ka);
                ldsm4(al[mi], aLo + mi * 2048 + ka);
            }
#pragma unroll
            for (int nj = 0; nj < WN / 16; ++nj) {
                ldsm4(bh[nj], bHi + nj * 2048 + kb2);
                ldsm4(bl[nj], bLo + nj * 2048 + kb2);
            }
#pragma unroll
            for (int mi = 0; mi < WM / 16; ++mi)
#pragma unroll
                for (int ni = 0; ni < WN / 8; ++ni)
                    mma16816(acc[mi][ni], ah[mi],
                             bh[ni >> 1][2 * (ni & 1)], bh[ni >> 1][2 * (ni & 1) + 1]);
#pragma unroll
            for (int mi = 0; mi < WM / 16; ++mi)
#pragma unroll
                for (int ni = 0; ni < WN / 8; ++ni)
                    mma16816(acc[mi][ni], ah[mi],
                             bl[ni >> 1][2 * (ni & 1)], bl[ni >> 1][2 * (ni & 1) + 1]);
#pragma unroll
            for (int mi = 0; mi < WM / 16; ++mi)
#pragma unroll
                for (int ni = 0; ni < WN / 8; ++ni)
                    mma16816(acc[mi][ni], al[mi],
                             bh[ni >> 1][2 * (ni & 1)], bh[ni >> 1][2 * (ni & 1) + 1]);
        }
        __syncthreads();
    }

    const int g = lane >> 2, tg = lane & 3;
#pragma unroll
    for (int mi = 0; mi < WM / 16; ++mi) {
#pragma unroll
        for (int ni = 0; ni < WN / 8; ++ni) {
            const size_t r0 = bm + (size_t)(wm + mi * 16 + g);
            const size_t r1 = r0 + 8;
            const int c0 = bn + wn + ni * 8 + 2 * tg;
            float b0 = bih[c0] + bhh[c0];
            float b1 = bih[c0 + 1] + bhh[c0 + 1];
            *(float2*)(out_f + r0 * HH + c0) =
                make_float2(acc[mi][ni][0] + b0, acc[mi][ni][1] + b1);
            *(float2*)(out_f + r1 * HH + c0) =
                make_float2(acc[mi][ni][2] + b0, acc[mi][ni][3] + b1);
        }
    }
}

// -------------------- persistent recurrence kernel -------------------------
// 128 CTAs x 256 threads; two independent 128-thread halves per CTA.
// Round-10 structure + EAGER per-chunk exchange: threads 0-6 of each half
// poll one producer flag each and publish readiness through release/acquire
// smem counters; loaders issue each chunk's cp.asyncs the moment that chunk's
// producer is done (overlapping straggler epilogues with loads).
#define NCTA 128
#define SMB 0                 // W_hh: hi [0,64K), lo [64K,128K); chunk stride 8K
#define SMB_SPLIT 65536
#define SMB_CHUNK 8192
#define SMA 131072            // A: + half*32768 + chunk*4096 (hi +0, lo +2048)
#define SMA_HALF 32768
#define SMA_CHUNK 4096
#define SMXP 196608           // xp: + half*4096 (16x64 f32)
#define SMMISC 204800         // [0,8): fb per half; [16,80): sready[2][8]
#define PSMEM 204928

__global__ void __launch_bounds__(256, 1)
rnn_persistent_kernel(const float* __restrict__ xp,
                      const __nv_bfloat16* __restrict__ whh_h,
                      const __nv_bfloat16* __restrict__ whh_l,
                      __nv_bfloat16* __restrict__ hhi_base,
                      __nv_bfloat16* __restrict__ hlo_base,
                      float* __restrict__ out)
{
    extern __shared__ char smem[];
    const uint32_t sb = smem_u32(smem);
    const int tid = threadIdx.x;
    const int half = tid >> 7;
    const int htid = tid & 127;
    const int lane = tid & 31;
    const int gidx = blockIdx.x >> 3;       // 0..15
    const int ntile = blockIdx.x & 7;       // 0..7
    const int rg = gidx + half * 16;        // rowgroup 0..31
    const size_t bm = (size_t)rg * 16;      // global row base (16 rows)
    const int bn = ntile * 64;
    const int wn = (htid >> 5) * 16;        // 4 warps/half, WN=16
    const int barid = 1 + half;

    // OFFSETS (generic-pointer smem stores) vs ADDRESSES (ldsm/cp.async/spins)
    const uint32_t aOff  = (uint32_t)(SMA + half * SMA_HALF);
    const uint32_t aAddr = sb + aOff;
    const uint32_t selfOff = aOff + (uint32_t)(ntile * SMA_CHUNK);
    const uint32_t xpAddr  = sb + (uint32_t)(SMXP + half * 4096);
    const uint32_t srBase  = sb + (uint32_t)(SMMISC + 16 + half * 32);  // sready[j]*4

    if (htid == 0) {
        unsigned fb0;
        asm volatile("ld.volatile.global.u32 %0, [%1];"
                     : "=r"(fb0) : "l"(&g_flag[rg][ntile * 32]));
        *(unsigned*)(smem + SMMISC + half * 4) = fb0;
    }
    // init readiness counters (both halves' slots) to 0
    if (tid < 16) *(unsigned*)(smem + SMMISC + 16 + tid * 4) = 0;

    // ---- resident W_hh tiles (rows bn..bn+64, all K), both splits (full CTA)
#pragma unroll
    for (int i = 0; i < 32; ++i) {
        int v = i * 256 + tid;              // 8192 granules
        int split = v >> 12;
        int rem = v & 4095;
        int chunk = rem >> 9;
        int rr = rem & 511;
        int row = rr >> 3, gq = rr & 7;
        const __nv_bfloat16* src = (split ? whh_l : whh_h);
        uint32_t dst = sb + SMB + split * SMB_SPLIT + chunk * SMB_CHUNK
                     + row * 128 + (uint32_t)((gq * 16) ^ ((row & 7) * 16));
        cp16(dst, src + (size_t)(bn + row) * HH + chunk * 64 + gq * 8);
    }
    CP_COMMIT();

    // generic-pointer smem store of a 4B pair at (row, even col lc), swizzled.
    auto sts4 = [&](uint32_t base, int row, int lc, uint32_t val) {
        uint32_t bc = (uint32_t)(lc * 2);
        uint32_t off = (uint32_t)(row * 128)
                     + ((bc & ~15u) ^ (((uint32_t)(row & 7)) << 4)) + (bc & 15u);
        *(uint32_t*)(smem + base + off) = val;
    };

    // ---- step 0: h1 = tanh(xp_0) -> buf 0 + self smem chunk ---------------
#pragma unroll
    for (int i = 0; i < 2; ++i) {
        int v = i * 128 + htid;             // 256 float4 granules (16 rows x 16)
        int row = v >> 4, c4 = v & 15;
        const float4 x = *(const float4*)(xp + (bm + row) * HH + bn + c4 * 4);
        float v0 = fast_tanh(x.x), v1 = fast_tanh(x.y);
        float v2 = fast_tanh(x.z), v3 = fast_tanh(x.w);
        __nv_bfloat16 h0, l0, h1, l1, h2, l2, h3, l3;
        split1(v0, h0, l0); split1(v1, h1, l1);
        split1(v2, h2, l2); split1(v3, h3, l3);
        __nv_bfloat162 hp0(h0, h1), hp1(h2, h3), lp0(l0, l1), lp1(l2, l3);
        size_t off = (bm + row) * HH + bn + c4 * 4;
        *(uint2*)(hhi_base + off) = make_uint2(*(uint32_t*)&hp0, *(uint32_t*)&hp1);
        *(uint2*)(hlo_base + off) = make_uint2(*(uint32_t*)&lp0, *(uint32_t*)&lp1);
        sts4(selfOff, row, c4 * 4, *(uint32_t*)&hp0);
        sts4(selfOff, row, c4 * 4 + 2, *(uint32_t*)&hp1);
        sts4(selfOff + 2048, row, c4 * 4, *(uint32_t*)&lp0);
        sts4(selfOff + 2048, row, c4 * 4 + 2, *(uint32_t*)&lp1);
    }
    CP_WAIT(0);
    __syncthreads();                         // last full-CTA barrier
    const unsigned fb = *(const unsigned*)(smem + SMMISC + half * 4);
    if (htid == 0)
        asm volatile("red.release.gpu.global.add.u32 [%0], %1;"
                     :: "l"(&g_flag[rg][ntile * 32]), "r"(1u) : "memory");

    // ldmatrix lane geometry (16-row A tiles)
    const int sub = lane >> 3, li = lane & 7;
    const int arow = (sub & 1) * 8 + li;
    const int akb  = (sub >> 1) * 16;
    const int brow = (sub >> 1) * 8 + li;
    const int bkb  = (sub & 1) * 16;
    const uint32_t swx = (uint32_t)(li * 16);
    const int gl = lane >> 2, tg = lane & 3;

    for (int t = 1; t < TT; ++t) {
        const __nv_bfloat16* Ah = hhi_base + (size_t)((t - 1) & 1) * BH;
        const __nv_bfloat16* Al = hlo_base + (size_t)((t - 1) & 1) * BH;
        __nv_bfloat16* Oh = hhi_base + (size_t)(t & 1) * BH;
        __nv_bfloat16* Ol = hlo_base + (size_t)(t & 1) * BH;
        const float* xpt = xp + (size_t)t * BH;

        float acc[2][4];
#pragma unroll
        for (int ni = 0; ni < 2; ++ni)
#pragma unroll
            for (int q = 0; q < 4; ++q) acc[ni][q] = 0.0f;

        auto compute_chunk = [&](int c) {
            const uint32_t aHi = aAddr + c * SMA_CHUNK + (uint32_t)(arow * 128);
            const uint32_t aLo = aHi + 2048;
            const uint32_t bHi = sb + SMB + c * SMB_CHUNK + (uint32_t)((wn + brow) * 128);
            const uint32_t bLo = bHi + SMB_SPLIT;
#pragma unroll
            for (int kk = 0; kk < 4; ++kk) {
                const uint32_t ka  = (uint32_t)(kk * 32 + akb) ^ swx;
                const uint32_t kb2 = (uint32_t)(kk * 32 + bkb) ^ swx;
                uint32_t ah[4], al4[4], bh[4], bl[4];
                ldsm4(ah, aHi + ka);
                ldsm4(al4, aLo + ka);
                ldsm4(bh, bHi + kb2);
                ldsm4(bl, bLo + kb2);
#pragma unroll
                for (int ni = 0; ni < 2; ++ni)
                    mma16816(acc[ni], ah, bh[2 * ni], bh[2 * ni + 1]);
#pragma unroll
                for (int ni = 0; ni < 2; ++ni)
                    mma16816(acc[ni], ah, bl[2 * ni], bl[2 * ni + 1]);
#pragma unroll
                for (int ni = 0; ni < 2; ++ni)
                    mma16816(acc[ni], al4, bh[2 * ni], bh[2 * ni + 1]);
            }
        };

        // phase -1: issue xp tile load (group 1)
        {
#pragma unroll
            for (int i = 0; i < 2; ++i) {
                int v = i * 128 + htid;      // 256 granules (16 rows x 16)
                int row = v >> 4, gq = v & 15;
                cp16(xpAddr + row * 256 + gq * 16,
                     xpt + (bm + row) * HH + bn + gq * 4);
            }
            CP_COMMIT();
        }

        // phase 0: self chunk (A in smem from own previous epilogue)
        compute_chunk(ntile);

        // phase 1: EAGER poll + publish. Thread htid<7 polls producer
        // c = (ntile+1+htid)&7 (i.e. chunk index j = htid+1) and publishes
        // readiness with release semantics.
        if (htid < 7) {
            const int c = (ntile + 1 + htid) & 7;
            const unsigned* fl = &g_flag[rg][c * 32];
            const unsigned target = fb + (unsigned)t;
            unsigned v;
            do {
                asm volatile("ld.acquire.gpu.global.u32 %0, [%1];" : "=r"(v) : "l"(fl));
            } while ((int)(v - target) < 0);
            st_rel_shared(srBase + (uint32_t)((htid + 1) * 4), (unsigned)t);
        }

        // phase 2: eager per-chunk issue — each thread spins on chunk j's
        // readiness (acquire) then issues its granules for that chunk.
#pragma unroll
        for (int j = 1; j < 8; ++j) {
            const uint32_t sr = srBase + (uint32_t)(j * 4);
            while ((int)(ld_acq_shared(sr) - (unsigned)t) < 0) { }
            const int c = (ntile + j) & 7;
            const uint32_t base = aAddr + c * SMA_CHUNK;
#pragma unroll
            for (int i = 0; i < 2; ++i) {
                int v = i * 128 + htid;      // 256 granules (hi 128 + lo 128)
                int split = v >> 7;
                int rr = v & 127;
                int row = rr >> 3, gq = rr & 7;
                const __nv_bfloat16* src = (split ? Al : Ah);
                uint32_t dst = base + split * 2048 + row * 128
                             + (uint32_t)((gq * 16) ^ ((row & 7) * 16));
                cp16(dst, src + (bm + (size_t)row) * HH + c * 64 + gq * 8);
            }
            CP_COMMIT();
        }

        // phase 3: two-stage waits + peer chunk computes
        CP_WAIT(4);      // xp + chunks j=1..3 complete
        BARH(barid);
        compute_chunk((ntile + 1) & 7);
        compute_chunk((ntile + 2) & 7);
        compute_chunk((ntile + 3) & 7);
        CP_WAIT(0);      // all complete
        BARH(barid);
        compute_chunk((ntile + 4) & 7);
        compute_chunk((ntile + 5) & 7);
        compute_chunk((ntile + 6) & 7);
        compute_chunk((ntile + 7) & 7);

        // phase 4: epilogue — tanh(acc + xp); write h (or final out)
        const float* sXP = (const float*)(smem + SMXP + half * 4096);
#pragma unroll
        for (int ni = 0; ni < 2; ++ni) {
            const int lr0 = gl;              // rows 0..7 and +8
            const int lc  = wn + ni * 8 + 2 * tg;
            const size_t r0 = bm + (size_t)lr0;
            const size_t r1 = r0 + 8;
            const int c0 = bn + lc;
            float2 x0 = *(const float2*)(sXP + lr0 * 64 + lc);
            float2 x1 = *(const float2*)(sXP + (lr0 + 8) * 64 + lc);
            float v0 = fast_tanh(acc[ni][0] + x0.x);
            float v1 = fast_tanh(acc[ni][1] + x0.y);
            float v2 = fast_tanh(acc[ni][2] + x1.x);
            float v3 = fast_tanh(acc[ni][3] + x1.y);
            if (t == TT - 1) {
                *(float2*)(out + r0 * HH + c0) = make_float2(v0, v1);
                *(float2*)(out + r1 * HH + c0) = make_float2(v2, v3);
            } else {
                __nv_bfloat16 h0, l0, h1, l1, h2, l2, h3, l3;
                split1(v0, h0, l0); split1(v1, h1, l1);
                split1(v2, h2, l2); split1(v3, h3, l3);
                __nv_bfloat162 hp0(h0, h1), hp1(h2, h3), lp0(l0, l1), lp1(l2, l3);
                *(uint32_t*)(Oh + r0 * HH + c0) = *(uint32_t*)&hp0;
                *(uint32_t*)(Ol + r0 * HH + c0) = *(uint32_t*)&lp0;
                *(uint32_t*)(Oh + r1 * HH + c0) = *(uint32_t*)&hp1;
                *(uint32_t*)(Ol + r1 * HH + c0) = *(uint32_t*)&lp1;
                sts4(selfOff, lr0, lc, *(uint32_t*)&hp0);
                sts4(selfOff + 2048, lr0, lc, *(uint32_t*)&lp0);
                sts4(selfOff, lr0 + 8, lc, *(uint32_t*)&hp1);
                sts4(selfOff + 2048, lr0 + 8, lc, *(uint32_t*)&lp1);
            }
        }

        BARH(barid);   // all of this half's STG/STS done
        if (htid == 0 && t < TT - 1)
            asm volatile("red.release.gpu.global.add.u32 [%0], %1;"
                         :: "l"(&g_flag[rg][ntile * 32]), "r"(1u) : "memory");
    }
}

// -------------------- launcher ---------------------------------------------
extern "C" void kernel_launch(void* const* d_in, const int* in_sizes, int n_in,
                              void* d_out, int out_size)
{
    const float* X   = (const float*)d_in[0];
    const float* Wih = (const float*)d_in[1];
    const float* Whh = (const float*)d_in[2];
    const float* bih = (const float*)d_in[3];
    const float* bhh = (const float*)d_in[4];
    float* out = (float*)d_out;

    float* xp;
    __nv_bfloat16 *xhi, *xlo, *wih_h, *wih_l, *whh_h, *whh_l, *hhi, *hlo;
    cudaGetSymbolAddress((void**)&xp, g_xp);
    cudaGetSymbolAddress((void**)&xhi, g_xhi);
    cudaGetSymbolAddress((void**)&xlo, g_xlo);
    cudaGetSymbolAddress((void**)&wih_h, g_wih_h);
    cudaGetSymbolAddress((void**)&wih_l, g_wih_l);
    cudaGetSymbolAddress((void**)&whh_h, g_whh_h);
    cudaGetSymbolAddress((void**)&whh_l, g_whh_l);
    cudaGetSymbolAddress((void**)&hhi, g_hhi);
    cudaGetSymbolAddress((void**)&hlo, g_hlo);

    constexpr int SMEM_XP = 2 * (2 * 64 * 128 + 2 * 128 * 128);  // 98304
    cudaFuncSetAttribute(gemm_split_kernel<64, 128, 32, 32>,
                         cudaFuncAttributeMaxDynamicSharedMemorySize, SMEM_XP);
    cudaFuncSetAttribute(rnn_persistent_kernel,
                         cudaFuncAttributeMaxDynamicSharedMemorySize, PSMEM);

    // 1) hi/lo splits
    split_kernel<<<128, 256>>>(Wih, wih_h, wih_l, HH * DD / 4);
    split_kernel<<<128, 256>>>(Whh, whh_h, whh_l, HH * HH / 4);
    split_kernel<<<16384, 256>>>(X, xhi, xlo, (int)((size_t)TT * BB * DD / 4));

    // 2) xp = X @ Wih^T + (b_ih + b_hh)
    {
        dim3 g(HH / 128, (TT * BB) / 64);  // (4, 4096)
        gemm_split_kernel<64, 128, 32, 32><<<g, 256, SMEM_XP>>>(
            xhi, xlo, wih_h, wih_l, bih, bhh, xp);
    }

    // 3) entire recurrence in one persistent kernel (dual half-CTAs, eager exchange)
    rnn_persistent_kernel<<<NCTA, 256, PSMEM>>>(xp, whh_h, whh_l, hhi, hlo, out);
}